// round 2
// baseline (speedup 1.0000x reference)
#include <cuda_runtime.h>

#define N_SEQ 2048
#define D_H   64
#define C_DIM 512
#define N_BH  16
#define SS_STRIDE 2052   // 2048 + 4 pad: breaks 32-bank aliasing between q-rows

// Scratch (device globals: no allocation allowed)
__device__ float g_Q[N_BH * N_SEQ * D_H];
__device__ float g_K[N_BH * N_SEQ * D_H];
__device__ float g_V[N_BH * N_SEQ * D_H];
__device__ float g_P[2 * N_SEQ * C_DIM];

// ---------------------------------------------------------------------------
// Y = X @ W^T + bias.  X:[M,512] row-major, W:[512,512] row-major.
// qkv_mode=1: scatter y[m,j] -> Y[((b*8+h)*2048+n)*64 + d]  (b=m>>11,n=m&2047,h=j>>6,d=j&63)
// qkv_mode=0: flat Y[m*512 + j]
// Tile 64x64, BK=16, 4x4 micro-tile, float4 shared reads (FMA-bound).
// ---------------------------------------------------------------------------
__global__ __launch_bounds__(256)
void gemm_bias_kernel(const float* __restrict__ X, const float* __restrict__ W,
                      const float* __restrict__ bias, float* __restrict__ Y,
                      int qkv_mode)
{
    __shared__ float sA[16 * 68];   // transposed: sA[c][m], pad 68
    __shared__ float sB[16 * 68];   // transposed: sB[c][j]

    const int tid = threadIdx.x;
    const int m0 = blockIdx.x * 64;
    const int j0 = blockIdx.y * 64;
    const int ty = tid >> 4;          // 0..15 (m micro-group)
    const int tx = tid & 15;          // 0..15 (j micro-group)
    const int lr = tid >> 2;          // 0..63 tile row for loads
    const int lc = (tid & 3) << 2;    // 0,4,8,12 col base

    float acc[4][4];
#pragma unroll
    for (int i = 0; i < 4; i++)
#pragma unroll
        for (int j = 0; j < 4; j++) acc[i][j] = 0.f;

    for (int kk = 0; kk < 512; kk += 16) {
        float4 av = *(const float4*)(X + (size_t)(m0 + lr) * 512 + kk + lc);
        float4 bv = *(const float4*)(W + (size_t)(j0 + lr) * 512 + kk + lc);
        sA[(lc + 0) * 68 + lr] = av.x; sA[(lc + 1) * 68 + lr] = av.y;
        sA[(lc + 2) * 68 + lr] = av.z; sA[(lc + 3) * 68 + lr] = av.w;
        sB[(lc + 0) * 68 + lr] = bv.x; sB[(lc + 1) * 68 + lr] = bv.y;
        sB[(lc + 2) * 68 + lr] = bv.z; sB[(lc + 3) * 68 + lr] = bv.w;
        __syncthreads();
#pragma unroll
        for (int c = 0; c < 16; ++c) {
            float4 a4 = *(const float4*)&sA[c * 68 + ty * 4];
            float4 b4 = *(const float4*)&sB[c * 68 + tx * 4];
            float a[4] = {a4.x, a4.y, a4.z, a4.w};
            float b[4] = {b4.x, b4.y, b4.z, b4.w};
#pragma unroll
            for (int i = 0; i < 4; i++)
#pragma unroll
                for (int j = 0; j < 4; j++)
                    acc[i][j] += a[i] * b[j];
        }
        __syncthreads();
    }

    float4 bb = *(const float4*)(bias + j0 + tx * 4);
#pragma unroll
    for (int i = 0; i < 4; i++) {
        const int m = m0 + ty * 4 + i;
        float4 r;
        r.x = acc[i][0] + bb.x; r.y = acc[i][1] + bb.y;
        r.z = acc[i][2] + bb.z; r.w = acc[i][3] + bb.w;
        if (qkv_mode) {
            const int b = m >> 11, n = m & 2047;
            const int h = j0 >> 6;
            *(float4*)(Y + ((size_t)(b * 8 + h) * 2048 + n) * 64 + tx * 4) = r;
        } else {
            *(float4*)(Y + (size_t)m * 512 + j0 + tx * 4) = r;
        }
    }
}

// ---------------------------------------------------------------------------
// Fused attention: per CTA = (bh, 16 q-rows).
//   Phase 1: S = Q Kt * 0.125  into shared (16 x 2048 fp32)
//   Phase 2: sparsemax per row (Newton on tau; exact fixed point of the
//            sort/cumsum formula), write attn to d_out
//   Phase 3: P = attn @ V  -> g_P in [B,N,C] layout
// ---------------------------------------------------------------------------
__global__ __launch_bounds__(256)
void attn_kernel(float* __restrict__ attn_out)
{
    extern __shared__ float sm[];
    float* sS = sm;                        // 16 * 2052
    float* sQ = sm + 16 * SS_STRIDE;       // 16 * 68
    float* sK = sQ + 16 * 68;              // 256 * 68 (K chunks, V chunks, red buf)

    const int tid = threadIdx.x;
    const int bh  = blockIdx.y;
    const int q0  = blockIdx.x * 16;

    // load Q tile (16 x 64)
    {
        const int q = tid >> 4, d4 = tid & 15;
        float4 v = *(const float4*)(g_Q + ((size_t)(bh * N_SEQ + q0 + q)) * 64 + d4 * 4);
        *(float4*)&sQ[q * 68 + d4 * 4] = v;
    }

    const int qg  = tid >> 6;   // 0..3 : q micro-group (4 rows)
    const int kg  = tid & 63;   // 0..63: k lane (k cols = kg + 64*j)
    const int ldr = tid >> 4;   // loader row base
    const int ldc = tid & 15;   // loader col (float4)

    // ---------------- Phase 1: scores ----------------
    for (int kc = 0; kc < 8; ++kc) {
        __syncthreads();  // protect sK reuse + sQ readiness on first iter
#pragma unroll
        for (int t = 0; t < 16; ++t) {
            const int r = ldr + t * 16;
            float4 v = *(const float4*)(g_K + ((size_t)(bh * N_SEQ + kc * 256 + r)) * 64 + ldc * 4);
            *(float4*)&sK[r * 68 + ldc * 4] = v;
        }
        __syncthreads();

        float acc[4][4];
#pragma unroll
        for (int i = 0; i < 4; i++)
#pragma unroll
            for (int j = 0; j < 4; j++) acc[i][j] = 0.f;

#pragma unroll 4
        for (int d4 = 0; d4 < 16; ++d4) {
            float4 a4[4], b4[4];
#pragma unroll
            for (int i = 0; i < 4; i++) a4[i] = *(const float4*)&sQ[(qg * 4 + i) * 68 + d4 * 4];
#pragma unroll
            for (int j = 0; j < 4; j++) b4[j] = *(const float4*)&sK[(kg + 64 * j) * 68 + d4 * 4];
#pragma unroll
            for (int i = 0; i < 4; i++)
#pragma unroll
                for (int j = 0; j < 4; j++)
                    acc[i][j] += a4[i].x * b4[j].x + a4[i].y * b4[j].y
                               + a4[i].z * b4[j].z + a4[i].w * b4[j].w;
        }
#pragma unroll
        for (int i = 0; i < 4; i++)
#pragma unroll
            for (int j = 0; j < 4; j++)
                sS[(qg * 4 + i) * SS_STRIDE + kc * 256 + kg + 64 * j] = acc[i][j] * 0.125f;
    }
    __syncthreads();

    // ---------------- Phase 2: sparsemax (one row per warp, twice) ----------------
    {
        const int warp = tid >> 5, lane = tid & 31;
#pragma unroll
        for (int rr = 0; rr < 2; ++rr) {
            const int q = warp + rr * 8;
            float* row = &sS[q * SS_STRIDE];

            float m = -3.402823466e38f;
            for (int t = 0; t < 64; ++t) m = fmaxf(m, row[lane + 32 * t]);
#pragma unroll
            for (int o = 16; o; o >>= 1) m = fmaxf(m, __shfl_xor_sync(0xffffffffu, m, o));

            // Newton on f(tau) = sum relu(s - tau) - 1, start tau = m-1 (f >= 0).
            // Convex piecewise-linear => monotone convergence to the exact
            // sparsemax threshold tau = (sum_support s - 1)/k.
            float tau = m - 1.0f;
            for (int it = 0; it < 64; ++it) {
                float S = 0.f; int cnt = 0;
                for (int t = 0; t < 64; ++t) {
                    float v = row[lane + 32 * t] - tau;
                    if (v > 0.f) { S += v; cnt++; }
                }
#pragma unroll
                for (int o = 16; o; o >>= 1) {
                    S   += __shfl_xor_sync(0xffffffffu, S, o);
                    cnt += __shfl_xor_sync(0xffffffffu, cnt, o);
                }
                if (cnt == 0) break;
                const float delta = (S - 1.0f) / (float)cnt;
                tau += delta;
                if (fabsf(delta) < 1e-8f) break;
            }

            for (int t = 0; t < 64; ++t) {
                const int k = lane + 32 * t;
                const float v = fmaxf(row[k] - tau, 0.f);
                row[k] = v;
                if (attn_out)
                    attn_out[((size_t)(bh * N_SEQ + q0 + q)) * N_SEQ + k] = v;
            }
        }
    }
    __syncthreads();

    // ---------------- Phase 3: P = attn @ V ----------------
    {
        const int ks  = tid >> 6;        // 0..3 : k-range split
        const int rem = tid & 63;
        const int qg3 = rem >> 4;        // 0..3 : q micro-group
        const int d4  = rem & 15;        // 0..15: output float4 column
        float4 acc4[4];
#pragma unroll
        for (int i = 0; i < 4; i++) acc4[i] = make_float4(0.f, 0.f, 0.f, 0.f);

        for (int kc = 0; kc < 8; ++kc) {
            __syncthreads();
#pragma unroll
            for (int t = 0; t < 16; ++t) {
                const int r = ldr + t * 16;
                float4 v = *(const float4*)(g_V + ((size_t)(bh * N_SEQ + kc * 256 + r)) * 64 + ldc * 4);
                *(float4*)&sK[r * 68 + ldc * 4] = v;
            }
            __syncthreads();
#pragma unroll 4
            for (int t = 0; t < 64; ++t) {
                const int k = ks * 64 + t;
                float4 v4 = *(const float4*)&sK[k * 68 + d4 * 4];
#pragma unroll
                for (int i = 0; i < 4; i++) {
                    const float a = sS[(qg3 * 4 + i) * SS_STRIDE + kc * 256 + k];
                    acc4[i].x += a * v4.x; acc4[i].y += a * v4.y;
                    acc4[i].z += a * v4.z; acc4[i].w += a * v4.w;
                }
            }
        }
        __syncthreads();
        float4* sRed = (float4*)sK;   // 4 * 16 * 16 float4 = 16 KB, fits in sK
#pragma unroll
        for (int i = 0; i < 4; i++)
            sRed[(ks * 16 + qg3 * 4 + i) * 16 + d4] = acc4[i];
        __syncthreads();
        {
            const int q = tid >> 4, dd = tid & 15;
            float4 r0 = sRed[(0 * 16 + q) * 16 + dd];
            float4 r1 = sRed[(1 * 16 + q) * 16 + dd];
            float4 r2 = sRed[(2 * 16 + q) * 16 + dd];
            float4 r3 = sRed[(3 * 16 + q) * 16 + dd];
            float4 r;
            r.x = (r0.x + r1.x) + (r2.x + r3.x);
            r.y = (r0.y + r1.y) + (r2.y + r3.y);
            r.z = (r0.z + r1.z) + (r2.z + r3.z);
            r.w = (r0.w + r1.w) + (r2.w + r3.w);
            const int b = bh >> 3, h = bh & 7;
            *(float4*)(g_P + ((size_t)(b * N_SEQ + q0 + q)) * C_DIM + h * 64 + dd * 4) = r;
        }
    }
}

// ---------------------------------------------------------------------------
extern "C" void kernel_launch(void* const* d_in, const int* in_sizes, int n_in,
                              void* d_out, int out_size)
{
    const float* x  = (const float*)d_in[0];
    const float* Wq = (const float*)d_in[1];
    const float* bq = (const float*)d_in[2];
    const float* Wk = (const float*)d_in[3];
    const float* bk = (const float*)d_in[4];
    const float* Wv = (const float*)d_in[5];
    const float* bv = (const float*)d_in[6];
    const float* Wo = (const float*)d_in[7];
    const float* bo = (const float*)d_in[8];

    float *dQ, *dK, *dV, *dP;
    cudaGetSymbolAddress((void**)&dQ, g_Q);
    cudaGetSymbolAddress((void**)&dK, g_K);
    cudaGetSymbolAddress((void**)&dV, g_V);
    cudaGetSymbolAddress((void**)&dP, g_P);

    float* out = (float*)d_out;
    const long long OUT_N = 2LL * N_SEQ * C_DIM;             // 2,097,152
    const long long ATT_N = (long long)N_BH * N_SEQ * N_SEQ; // 67,108,864
    float* final_ptr = nullptr;
    float* attn_ptr  = nullptr;
    if ((long long)out_size >= OUT_N + ATT_N) { final_ptr = out; attn_ptr = out + OUT_N; }
    else if ((long long)out_size >= ATT_N)    { attn_ptr = out; }
    else                                      { final_ptr = out; }

    dim3 gA(64, 8);
    gemm_bias_kernel<<<gA, 256>>>(x, Wq, bq, dQ, 1);
    gemm_bias_kernel<<<gA, 256>>>(x, Wk, bk, dK, 1);
    gemm_bias_kernel<<<gA, 256>>>(x, Wv, bv, dV, 1);

    const int smem = (16 * SS_STRIDE + 16 * 68 + 256 * 68) * 4;  // 205,312 B
    cudaFuncSetAttribute(attn_kernel, cudaFuncAttributeMaxDynamicSharedMemorySize, smem);
    attn_kernel<<<dim3(128, 16), 256, smem>>>(attn_ptr);

    if (final_ptr)
        gemm_bias_kernel<<<gA, 256>>>(dP, Wo, bo, final_ptr, 0);
}

// round 4
// speedup vs baseline: 1.4108x; 1.4108x over previous
#include <cuda_runtime.h>
#include <cstdint>

#define N_SEQ 2048
#define C_DIM 512
#define N_BH  16

__device__ float g_Q[N_BH * N_SEQ * 64];
__device__ float g_K[N_BH * N_SEQ * 64];
__device__ float g_V[N_BH * N_SEQ * 64];
__device__ float g_P[2 * N_SEQ * C_DIM];
__device__ float g_S[(size_t)N_BH * N_SEQ * N_SEQ];  // fallback if attn not an output

// ============================ helpers ============================
__device__ __forceinline__ uint32_t f2tf(float x) {
    uint32_t r; asm("cvt.rna.tf32.f32 %0, %1;" : "=r"(r) : "f"(x)); return r;
}
__device__ __forceinline__ void mma8(float* d, const uint32_t* a, const uint32_t* b) {
    asm volatile(
        "mma.sync.aligned.m16n8k8.row.col.f32.tf32.tf32.f32 "
        "{%0,%1,%2,%3}, {%4,%5,%6,%7}, {%8,%9}, {%0,%1,%2,%3};"
        : "+f"(d[0]), "+f"(d[1]), "+f"(d[2]), "+f"(d[3])
        : "r"(a[0]), "r"(a[1]), "r"(a[2]), "r"(a[3]), "r"(b[0]), "r"(b[1]));
}
// split float4 -> tf32 hi/lo, store both as float4
__device__ __forceinline__ void split_st(float4 v, float* hi, float* lo) {
    uint32_t hx = f2tf(v.x), hy = f2tf(v.y), hz = f2tf(v.z), hw = f2tf(v.w);
    *(float4*)hi = make_float4(__uint_as_float(hx), __uint_as_float(hy),
                               __uint_as_float(hz), __uint_as_float(hw));
    *(float4*)lo = make_float4(
        __uint_as_float(f2tf(v.x - __uint_as_float(hx))),
        __uint_as_float(f2tf(v.y - __uint_as_float(hy))),
        __uint_as_float(f2tf(v.z - __uint_as_float(hz))),
        __uint_as_float(f2tf(v.w - __uint_as_float(hw))));
}
__device__ __forceinline__ void lda4(uint32_t* a, const float* p, int stride) {
    a[0] = __float_as_uint(p[0]);
    a[1] = __float_as_uint(p[8 * stride]);
    a[2] = __float_as_uint(p[4]);
    a[3] = __float_as_uint(p[8 * stride + 4]);
}

// ======================= projection GEMM (3xTF32 mma) =======================
// Y = X @ W^T + bias.  X:[M,512], W:[N,512] row-major (both K-major).
// CTA: 128m x 128n tile, K chunks of 64. 8 warps, warp = 16m x 128n.
#define PJ_SMEM ((4 * 128 * 68) * 4)   // 139,264 B

__global__ __launch_bounds__(256)
void proj_kernel(const float* __restrict__ X, const float* __restrict__ W,
                 const float* __restrict__ bias, float* __restrict__ Y, int qkv_mode)
{
    extern __shared__ float sm[];
    float* sXh = sm;
    float* sXl = sXh + 128 * 68;
    float* sWh = sXl + 128 * 68;
    float* sWl = sWh + 128 * 68;

    const int tid = threadIdx.x;
    const int m0 = blockIdx.x * 128, n0 = blockIdx.y * 128;
    const int w = tid >> 5, lane = tid & 31;
    const int g = lane >> 2, t4 = lane & 3;
    const int lr = tid >> 1, lcb = (tid & 1) * 32;

    float acc[16][4];
#pragma unroll
    for (int i = 0; i < 16; i++)
#pragma unroll
        for (int j = 0; j < 4; j++) acc[i][j] = 0.f;

    for (int kk = 0; kk < 512; kk += 64) {
        __syncthreads();
        {
            const float4* xs = (const float4*)(X + (size_t)(m0 + lr) * 512 + kk + lcb);
            const float4* ws = (const float4*)(W + (size_t)(n0 + lr) * 512 + kk + lcb);
#pragma unroll
            for (int i = 0; i < 8; i++) {
                const int c = lcb + i * 4;
                split_st(xs[i], &sXh[lr * 68 + c], &sXl[lr * 68 + c]);
                split_st(ws[i], &sWh[lr * 68 + c], &sWl[lr * 68 + c]);
            }
        }
        __syncthreads();
#pragma unroll
        for (int kf = 0; kf < 8; kf++) {
            uint32_t ah[4], al[4];
            const int ao = (w * 16 + g) * 68 + kf * 8 + t4;
            lda4(ah, sXh + ao, 68);
            lda4(al, sXl + ao, 68);
#pragma unroll
            for (int nf = 0; nf < 16; nf++) {
                const int bo = (nf * 8 + g) * 68 + kf * 8 + t4;
                uint32_t bh2[2] = {__float_as_uint(sWh[bo]), __float_as_uint(sWh[bo + 4])};
                uint32_t bl2[2] = {__float_as_uint(sWl[bo]), __float_as_uint(sWl[bo + 4])};
                mma8(acc[nf], ah, bh2);
                mma8(acc[nf], al, bh2);
                mma8(acc[nf], ah, bl2);
            }
        }
    }

    const int m = m0 + w * 16 + g;      // row for c0/c1; +8 for c2/c3
#pragma unroll
    for (int nf = 0; nf < 16; nf++) {
        const int j = n0 + nf * 8 + t4 * 2;
        const float bx = bias[j], by = bias[j + 1];
        float2 v0 = make_float2(acc[nf][0] + bx, acc[nf][1] + by);
        float2 v1 = make_float2(acc[nf][2] + bx, acc[nf][3] + by);
        if (qkv_mode) {
            const int b = m >> 11, n = m & 2047;
            const int h = j >> 6, d = j & 63;
            *(float2*)(Y + ((size_t)(b * 8 + h) * 2048 + n) * 64 + d) = v0;
            *(float2*)(Y + ((size_t)(b * 8 + h) * 2048 + n + 8) * 64 + d) = v1;
        } else {
            *(float2*)(Y + (size_t)m * 512 + j) = v0;
            *(float2*)(Y + (size_t)(m + 8) * 512 + j) = v1;
        }
    }
}

// ======================= scores kernel (3xTF32 mma) =======================
// S[q, :] = (Q K^T)/8.  CTA: (bh, 128 q-rows), 16 k-tiles of 128.
#define SC_SMEM ((4 * 128 * 68) * 4)   // 139,264 B

__global__ __launch_bounds__(256)
void scores_kernel(float* __restrict__ S)
{
    extern __shared__ float sm[];
    float* sQh = sm;
    float* sQl = sQh + 128 * 68;
    float* sKh = sQl + 128 * 68;
    float* sKl = sKh + 128 * 68;

    const int tid = threadIdx.x;
    const int bh = blockIdx.y, q0 = blockIdx.x * 128;
    const int w = tid >> 5, lane = tid & 31;
    const int g = lane >> 2, t4 = lane & 3;
    const int lr = tid >> 1, lcb = (tid & 1) * 32;

    {   // Q tile, scale 1/8 folded in
        const float4* qs = (const float4*)(g_Q + ((size_t)bh * N_SEQ + q0 + lr) * 64 + lcb);
#pragma unroll
        for (int i = 0; i < 8; i++) {
            float4 v = qs[i];
            v.x *= 0.125f; v.y *= 0.125f; v.z *= 0.125f; v.w *= 0.125f;
            const int c = lcb + i * 4;
            split_st(v, &sQh[lr * 68 + c], &sQl[lr * 68 + c]);
        }
    }

    for (int kt = 0; kt < 16; kt++) {
        __syncthreads();
        {
            const float4* ks = (const float4*)(g_K + ((size_t)bh * N_SEQ + kt * 128 + lr) * 64 + lcb);
#pragma unroll
            for (int i = 0; i < 8; i++) {
                const int c = lcb + i * 4;
                split_st(ks[i], &sKh[lr * 68 + c], &sKl[lr * 68 + c]);
            }
        }
        __syncthreads();

        float acc[16][4];
#pragma unroll
        for (int i = 0; i < 16; i++)
#pragma unroll
            for (int j = 0; j < 4; j++) acc[i][j] = 0.f;

#pragma unroll
        for (int kf = 0; kf < 8; kf++) {
            uint32_t ah[4], al[4];
            const int ao = (w * 16 + g) * 68 + kf * 8 + t4;
            lda4(ah, sQh + ao, 68);
            lda4(al, sQl + ao, 68);
#pragma unroll
            for (int nf = 0; nf < 16; nf++) {
                const int bo = (nf * 8 + g) * 68 + kf * 8 + t4;
                uint32_t bh2[2] = {__float_as_uint(sKh[bo]), __float_as_uint(sKh[bo + 4])};
                uint32_t bl2[2] = {__float_as_uint(sKl[bo]), __float_as_uint(sKl[bo + 4])};
                mma8(acc[nf], ah, bh2);
                mma8(acc[nf], al, bh2);
                mma8(acc[nf], ah, bl2);
            }
        }

        float* dst0 = S + ((size_t)(bh * N_SEQ + q0 + w * 16 + g)) * N_SEQ + kt * 128;
        float* dst1 = dst0 + 8 * N_SEQ;
#pragma unroll
        for (int nf = 0; nf < 16; nf++) {
            const int c = nf * 8 + t4 * 2;
            *(float2*)(dst0 + c) = make_float2(acc[nf][0], acc[nf][1]);
            *(float2*)(dst1 + c) = make_float2(acc[nf][2], acc[nf][3]);
        }
    }
}

// ======================= sparsemax kernel =======================
// One row per warp, whole 2048-row in registers; Newton on tau (exact fixed
// point of the sort/cumsum formula). In-place.
__global__ __launch_bounds__(256)
void sparsemax_kernel(float* __restrict__ A)
{
    const int lane = threadIdx.x & 31;
    const size_t row = (size_t)blockIdx.x * 8 + (threadIdx.x >> 5);
    float4* r = (float4*)(A + row * N_SEQ);
    float4 v[16];
#pragma unroll
    for (int i = 0; i < 16; i++) v[i] = r[i * 32 + lane];

    float m = -3.402823466e38f;
#pragma unroll
    for (int i = 0; i < 16; i++)
        m = fmaxf(m, fmaxf(fmaxf(v[i].x, v[i].y), fmaxf(v[i].z, v[i].w)));
#pragma unroll
    for (int o = 16; o; o >>= 1) m = fmaxf(m, __shfl_xor_sync(0xffffffffu, m, o));

    float tau = m - 1.0f;
    for (int it = 0; it < 64; ++it) {
        float Ss = 0.f; int cnt = 0;
#pragma unroll
        for (int i = 0; i < 16; i++) {
            float d;
            d = v[i].x - tau; if (d > 0.f) { Ss += d; cnt++; }
            d = v[i].y - tau; if (d > 0.f) { Ss += d; cnt++; }
            d = v[i].z - tau; if (d > 0.f) { Ss += d; cnt++; }
            d = v[i].w - tau; if (d > 0.f) { Ss += d; cnt++; }
        }
#pragma unroll
        for (int o = 16; o; o >>= 1) {
            Ss  += __shfl_xor_sync(0xffffffffu, Ss, o);
            cnt += __shfl_xor_sync(0xffffffffu, cnt, o);
        }
        if (cnt == 0) break;
        const float delta = (Ss - 1.0f) / (float)cnt;
        tau += delta;
        if (fabsf(delta) < 1e-8f) break;
    }
#pragma unroll
    for (int i = 0; i < 16; i++) {
        float4 o;
        o.x = fmaxf(v[i].x - tau, 0.f); o.y = fmaxf(v[i].y - tau, 0.f);
        o.z = fmaxf(v[i].z - tau, 0.f); o.w = fmaxf(v[i].w - tau, 0.f);
        r[i * 32 + lane] = o;
    }
}

// ======================= attn@V kernel (3xTF32 mma) =======================
// P[q,d] = sum_k attn[q,k] V[k,d].  CTA: (bh, 128 q), 16 k-tiles of 128, acc
// held in registers across the whole k loop (warp = 16q x 64d).
#define AV_SMEM ((2 * 128 * 132 + 2 * 128 * 72) * 4)   // 208,896 B

__global__ __launch_bounds__(256)
void attnv_kernel(const float* __restrict__ A)
{
    extern __shared__ float sm[];
    float* sAh = sm;                     // 128 x 132
    float* sAl = sAh + 128 * 132;
    float* sVh = sAl + 128 * 132;        // 128 x 72
    float* sVl = sVh + 128 * 72;

    const int tid = threadIdx.x;
    const int bh = blockIdx.y, q0 = blockIdx.x * 128;
    const int w = tid >> 5, lane = tid & 31;
    const int g = lane >> 2, t4 = lane & 3;
    const int lr = tid >> 1;
    const int lcb  = (tid & 1) * 32;     // V loader col base
    const int lcb2 = (tid & 1) * 64;     // A loader col base

    float acc[8][4];
#pragma unroll
    for (int i = 0; i < 8; i++)
#pragma unroll
        for (int j = 0; j < 4; j++) acc[i][j] = 0.f;

    for (int kt = 0; kt < 16; kt++) {
        __syncthreads();
        {
            const float4* as = (const float4*)(A + ((size_t)(bh * N_SEQ + q0 + lr)) * N_SEQ
                                               + kt * 128 + lcb2);
#pragma unroll
            for (int i = 0; i < 16; i++) {
                const int c = lcb2 + i * 4;
                split_st(as[i], &sAh[lr * 132 + c], &sAl[lr * 132 + c]);
            }
            const float4* vs = (const float4*)(g_V + ((size_t)bh * N_SEQ + kt * 128 + lr) * 64 + lcb);
#pragma unroll
            for (int i = 0; i < 8; i++) {
                const int c = lcb + i * 4;
                split_st(vs[i], &sVh[lr * 72 + c], &sVl[lr * 72 + c]);
            }
        }
        __syncthreads();

#pragma unroll
        for (int kf = 0; kf < 16; kf++) {
            uint32_t ah[4], al[4];
            const int ao = (w * 16 + g) * 132 + kf * 8 + t4;
            lda4(ah, sAh + ao, 132);
            lda4(al, sAl + ao, 132);
#pragma unroll
            for (int nf = 0; nf < 8; nf++) {
                // B = V^T: b0 = V[k = kf*8+t4][d = nf*8+g], b1 = k+4
                const int bo = (kf * 8 + t4) * 72 + nf * 8 + g;
                uint32_t bh2[2] = {__float_as_uint(sVh[bo]), __float_as_uint(sVh[bo + 4 * 72])};
                uint32_t bl2[2] = {__float_as_uint(sVl[bo]), __float_as_uint(sVl[bo + 4 * 72])};
                mma8(acc[nf], ah, bh2);
                mma8(acc[nf], al, bh2);
                mma8(acc[nf], ah, bl2);
            }
        }
    }

    const int b = bh >> 3, h = bh & 7;
    float* dst0 = g_P + ((size_t)(b * N_SEQ + q0 + w * 16 + g)) * C_DIM + h * 64;
    float* dst1 = dst0 + 8 * C_DIM;
#pragma unroll
    for (int nf = 0; nf < 8; nf++) {
        const int c = nf * 8 + t4 * 2;
        *(float2*)(dst0 + c) = make_float2(acc[nf][0], acc[nf][1]);
        *(float2*)(dst1 + c) = make_float2(acc[nf][2], acc[nf][3]);
    }
}

// ---------------------------------------------------------------------------
extern "C" void kernel_launch(void* const* d_in, const int* in_sizes, int n_in,
                              void* d_out, int out_size)
{
    const float* x  = (const float*)d_in[0];
    const float* Wq = (const float*)d_in[1];
    const float* bq = (const float*)d_in[2];
    const float* Wk = (const float*)d_in[3];
    const float* bk = (const float*)d_in[4];
    const float* Wv = (const float*)d_in[5];
    const float* bv = (const float*)d_in[6];
    const float* Wo = (const float*)d_in[7];
    const float* bo = (const float*)d_in[8];

    float *dQ, *dK, *dV, *dP, *dS;
    cudaGetSymbolAddress((void**)&dQ, g_Q);
    cudaGetSymbolAddress((void**)&dK, g_K);
    cudaGetSymbolAddress((void**)&dV, g_V);
    cudaGetSymbolAddress((void**)&dP, g_P);
    cudaGetSymbolAddress((void**)&dS, g_S);

    float* out = (float*)d_out;
    const long long OUT_N = 2LL * N_SEQ * C_DIM;
    const long long ATT_N = (long long)N_BH * N_SEQ * N_SEQ;
    float* final_ptr = nullptr;
    float* attn_ptr  = nullptr;
    if ((long long)out_size >= OUT_N + ATT_N) { final_ptr = out; attn_ptr = out + OUT_N; }
    else if ((long long)out_size >= ATT_N)    { attn_ptr = out; }
    else                                      { final_ptr = out; }
    float* S = attn_ptr ? attn_ptr : dS;

    cudaFuncSetAttribute(proj_kernel,   cudaFuncAttributeMaxDynamicSharedMemorySize, PJ_SMEM);
    cudaFuncSetAttribute(scores_kernel, cudaFuncAttributeMaxDynamicSharedMemorySize, SC_SMEM);
    cudaFuncSetAttribute(attnv_kernel,  cudaFuncAttributeMaxDynamicSharedMemorySize, AV_SMEM);

    dim3 gP(32, 4);
    proj_kernel<<<gP, 256, PJ_SMEM>>>(x, Wq, bq, dQ, 1);
    proj_kernel<<<gP, 256, PJ_SMEM>>>(x, Wk, bk, dK, 1);
    proj_kernel<<<gP, 256, PJ_SMEM>>>(x, Wv, bv, dV, 1);

    scores_kernel<<<dim3(16, 16), 256, SC_SMEM>>>(S);
    sparsemax_kernel<<<(N_BH * N_SEQ) / 8, 256>>>(S);
    attnv_kernel<<<dim3(16, 16), 256, AV_SMEM>>>(S);

    if (final_ptr)
        proj_kernel<<<gP, 256, PJ_SMEM>>>(dP, Wo, bo, final_ptr, 0);
}

// round 5
// speedup vs baseline: 1.5104x; 1.0706x over previous
#include <cuda_runtime.h>
#include <cstdint>

#define N_SEQ 2048
#define C_DIM 512
#define N_BH  16

__device__ float g_Q[N_BH * N_SEQ * 64];
__device__ float g_K[N_BH * N_SEQ * 64];
__device__ float g_V[N_BH * N_SEQ * 64];
__device__ float g_P[2 * N_SEQ * C_DIM];
__device__ float g_S[(size_t)N_BH * N_SEQ * N_SEQ];  // fallback if attn not an output

// ============================ helpers ============================
__device__ __forceinline__ uint32_t f2tf(float x) {
    uint32_t r; asm("cvt.rna.tf32.f32 %0, %1;" : "=r"(r) : "f"(x)); return r;
}
__device__ __forceinline__ uint32_t smem_u32(const void* p) {
    uint32_t a;
    asm("{ .reg .u64 t; cvta.to.shared.u64 t, %1; cvt.u32.u64 %0, t; }" : "=r"(a) : "l"(p));
    return a;
}
__device__ __forceinline__ void cp16(uint32_t s, const void* g) {
    asm volatile("cp.async.cg.shared.global [%0], [%1], 16;" :: "r"(s), "l"(g) : "memory");
}
#define CP_COMMIT() asm volatile("cp.async.commit_group;" ::: "memory")
#define CP_WAIT0()  asm volatile("cp.async.wait_group 0;" ::: "memory")

__device__ __forceinline__ void mma8(float* d, const uint32_t* a, const uint32_t* b) {
    asm volatile(
        "mma.sync.aligned.m16n8k8.row.col.f32.tf32.tf32.f32 "
        "{%0,%1,%2,%3}, {%4,%5,%6,%7}, {%8,%9}, {%0,%1,%2,%3};"
        : "+f"(d[0]), "+f"(d[1]), "+f"(d[2]), "+f"(d[3])
        : "r"(a[0]), "r"(a[1]), "r"(a[2]), "r"(a[3]), "r"(b[0]), "r"(b[1]));
}
__device__ __forceinline__ void cvt_hl(float x, uint32_t& h, uint32_t& l) {
    h = f2tf(x);
    l = f2tf(x - __uint_as_float(h));
}
// load raw A fragment (m16k8) from smem and split hi/lo in registers
__device__ __forceinline__ void lda_hl(uint32_t* h, uint32_t* l, const float* p, int st) {
    cvt_hl(p[0], h[0], l[0]);
    cvt_hl(p[8 * st], h[1], l[1]);
    cvt_hl(p[4], h[2], l[2]);
    cvt_hl(p[8 * st + 4], h[3], l[3]);
}
// 3xTF32 product: D += A*B with hi/lo compensation
__device__ __forceinline__ void mma3(float* acc, const uint32_t* ah, const uint32_t* al,
                                     const uint32_t* bh, const uint32_t* bl) {
    mma8(acc, ah, bh);
    mma8(acc, al, bh);
    mma8(acc, ah, bl);
}

// ======================= projection GEMM (3xTF32 mma) =======================
// Y = X @ W^T + bias.  CTA: 128m x 128n, K chunks of 64; 8 warps = 16m each.
// qkv_mode=1: blockIdx.z selects (W,b,dst) and scatters to [BH,N,D].
#define PJ_SMEM ((2 * 128 * 68) * 4)   // 69,632 B -> 2 CTAs/SM

__global__ __launch_bounds__(256, 2)
void proj_kernel(const float* __restrict__ X,
                 const float* __restrict__ W0, const float* __restrict__ W1,
                 const float* __restrict__ W2,
                 const float* __restrict__ b0, const float* __restrict__ b1,
                 const float* __restrict__ b2,
                 float* __restrict__ Y0, float* __restrict__ Y1, float* __restrict__ Y2,
                 int qkv_mode)
{
    extern __shared__ float sm[];
    float* sX = sm;                 // 128 x 68 raw fp32
    float* sW = sX + 128 * 68;
    const uint32_t sXa = smem_u32(sX), sWa = smem_u32(sW);

    const int z = blockIdx.z;
    const float* W = (z == 0) ? W0 : (z == 1) ? W1 : W2;
    const float* bias = (z == 0) ? b0 : (z == 1) ? b1 : b2;
    float* Y = (z == 0) ? Y0 : (z == 1) ? Y1 : Y2;

    const int tid = threadIdx.x;
    const int m0 = blockIdx.x * 128, n0 = blockIdx.y * 128;
    const int w = tid >> 5, lane = tid & 31;
    const int g = lane >> 2, t4 = lane & 3;
    const int lr = tid >> 1, lcb = (tid & 1) * 32;

    float acc[16][4];
#pragma unroll
    for (int i = 0; i < 16; i++)
#pragma unroll
        for (int j = 0; j < 4; j++) acc[i][j] = 0.f;

    for (int kk = 0; kk < 512; kk += 64) {
        const float* xs = X + (size_t)(m0 + lr) * 512 + kk + lcb;
        const float* ws = W + (size_t)(n0 + lr) * 512 + kk + lcb;
#pragma unroll
        for (int i = 0; i < 8; i++) {
            cp16(sXa + (lr * 68 + lcb + i * 4) * 4, xs + i * 4);
            cp16(sWa + (lr * 68 + lcb + i * 4) * 4, ws + i * 4);
        }
        CP_COMMIT();
        CP_WAIT0();
        __syncthreads();
#pragma unroll
        for (int kf = 0; kf < 8; kf++) {
            uint32_t ah[4], al[4];
            lda_hl(ah, al, sX + (w * 16 + g) * 68 + kf * 8 + t4, 68);
#pragma unroll
            for (int nf = 0; nf < 16; nf++) {
                const int bo = (nf * 8 + g) * 68 + kf * 8 + t4;
                uint32_t bh2[2], bl2[2];
                cvt_hl(sW[bo], bh2[0], bl2[0]);
                cvt_hl(sW[bo + 4], bh2[1], bl2[1]);
                mma3(acc[nf], ah, al, bh2, bl2);
            }
        }
        __syncthreads();
    }

    const int m = m0 + w * 16 + g;
#pragma unroll
    for (int nf = 0; nf < 16; nf++) {
        const int j = n0 + nf * 8 + t4 * 2;
        const float bx = bias[j], by = bias[j + 1];
        float2 v0 = make_float2(acc[nf][0] + bx, acc[nf][1] + by);
        float2 v1 = make_float2(acc[nf][2] + bx, acc[nf][3] + by);
        if (qkv_mode) {
            const int b = m >> 11, n = m & 2047;
            const int h = j >> 6, d = j & 63;
            *(float2*)(Y + ((size_t)(b * 8 + h) * 2048 + n) * 64 + d) = v0;
            *(float2*)(Y + ((size_t)(b * 8 + h) * 2048 + n + 8) * 64 + d) = v1;
        } else {
            *(float2*)(Y + (size_t)m * 512 + j) = v0;
            *(float2*)(Y + (size_t)(m + 8) * 512 + j) = v1;
        }
    }
}

// ======================= scores kernel (3xTF32 mma) =======================
// S[q,:] = (Q K^T)/8.  CTA: (bh, 128 q-rows) x 16 k-tiles of 128.
#define SC_SMEM ((2 * 128 * 68) * 4)   // 69,632 B -> 2 CTAs/SM

__global__ __launch_bounds__(256, 2)
void scores_kernel(float* __restrict__ S)
{
    extern __shared__ float sm[];
    float* sQ = sm;                 // 128 x 68 raw
    float* sK = sQ + 128 * 68;
    const uint32_t sQa = smem_u32(sQ), sKa = smem_u32(sK);

    const int tid = threadIdx.x;
    const int bh = blockIdx.y, q0 = blockIdx.x * 128;
    const int w = tid >> 5, lane = tid & 31;
    const int g = lane >> 2, t4 = lane & 3;
    const int lr = tid >> 1, lcb = (tid & 1) * 32;

    {   // Q tile (raw; 1/8 scale applied in epilogue, exact)
        const float* qs = g_Q + ((size_t)bh * N_SEQ + q0 + lr) * 64 + lcb;
#pragma unroll
        for (int i = 0; i < 8; i++)
            cp16(sQa + (lr * 68 + lcb + i * 4) * 4, qs + i * 4);
        CP_COMMIT();
    }

    for (int kt = 0; kt < 16; kt++) {
        const float* ks = g_K + ((size_t)bh * N_SEQ + kt * 128 + lr) * 64 + lcb;
#pragma unroll
        for (int i = 0; i < 8; i++)
            cp16(sKa + (lr * 68 + lcb + i * 4) * 4, ks + i * 4);
        CP_COMMIT();
        CP_WAIT0();
        __syncthreads();

        float acc[16][4];
#pragma unroll
        for (int i = 0; i < 16; i++)
#pragma unroll
            for (int j = 0; j < 4; j++) acc[i][j] = 0.f;

#pragma unroll
        for (int kf = 0; kf < 8; kf++) {
            uint32_t ah[4], al[4];
            lda_hl(ah, al, sQ + (w * 16 + g) * 68 + kf * 8 + t4, 68);
#pragma unroll
            for (int nf = 0; nf < 16; nf++) {
                const int bo = (nf * 8 + g) * 68 + kf * 8 + t4;
                uint32_t bh2[2], bl2[2];
                cvt_hl(sK[bo], bh2[0], bl2[0]);
                cvt_hl(sK[bo + 4], bh2[1], bl2[1]);
                mma3(acc[nf], ah, al, bh2, bl2);
            }
        }

        float* dst0 = S + ((size_t)(bh * N_SEQ + q0 + w * 16 + g)) * N_SEQ + kt * 128;
        float* dst1 = dst0 + 8 * N_SEQ;
#pragma unroll
        for (int nf = 0; nf < 16; nf++) {
            const int c = nf * 8 + t4 * 2;
            *(float2*)(dst0 + c) = make_float2(acc[nf][0] * 0.125f, acc[nf][1] * 0.125f);
            *(float2*)(dst1 + c) = make_float2(acc[nf][2] * 0.125f, acc[nf][3] * 0.125f);
        }
        __syncthreads();   // S writes use regs; sync protects sK reuse
    }
}

// ======================= sparsemax kernel =======================
// One row per warp, whole 2048-row in registers; Newton on tau (exact fixed
// point of the sort/cumsum formula). In-place.
__global__ __launch_bounds__(256)
void sparsemax_kernel(float* __restrict__ A)
{
    const int lane = threadIdx.x & 31;
    const size_t row = (size_t)blockIdx.x * 8 + (threadIdx.x >> 5);
    float4* r = (float4*)(A + row * N_SEQ);
    float4 v[16];
#pragma unroll
    for (int i = 0; i < 16; i++) v[i] = r[i * 32 + lane];

    float m = -3.402823466e38f;
#pragma unroll
    for (int i = 0; i < 16; i++)
        m = fmaxf(m, fmaxf(fmaxf(v[i].x, v[i].y), fmaxf(v[i].z, v[i].w)));
#pragma unroll
    for (int o = 16; o; o >>= 1) m = fmaxf(m, __shfl_xor_sync(0xffffffffu, m, o));

    float tau = m - 1.0f;
    for (int it = 0; it < 64; ++it) {
        float Ss = 0.f; int cnt = 0;
#pragma unroll
        for (int i = 0; i < 16; i++) {
            float d;
            d = v[i].x - tau; if (d > 0.f) { Ss += d; cnt++; }
            d = v[i].y - tau; if (d > 0.f) { Ss += d; cnt++; }
            d = v[i].z - tau; if (d > 0.f) { Ss += d; cnt++; }
            d = v[i].w - tau; if (d > 0.f) { Ss += d; cnt++; }
        }
#pragma unroll
        for (int o = 16; o; o >>= 1) {
            Ss  += __shfl_xor_sync(0xffffffffu, Ss, o);
            cnt += __shfl_xor_sync(0xffffffffu, cnt, o);
        }
        if (cnt == 0) break;
        const float delta = (Ss - 1.0f) / (float)cnt;
        tau += delta;
        if (fabsf(delta) < 1e-8f) break;
    }
#pragma unroll
    for (int i = 0; i < 16; i++) {
        float4 o;
        o.x = fmaxf(v[i].x - tau, 0.f); o.y = fmaxf(v[i].y - tau, 0.f);
        o.z = fmaxf(v[i].z - tau, 0.f); o.w = fmaxf(v[i].w - tau, 0.f);
        r[i * 32 + lane] = o;
    }
}

// ======================= attn@V kernel (3xTF32 mma) =======================
// P[q,d] = sum_k attn[q,k] V[k,d].  CTA: (bh, 128 q), 16 k-tiles of 128,
// acc in registers across the whole k loop (warp = 16q x 64d).
#define AV_SMEM ((128 * 132 + 128 * 72) * 4)   // 104,448 B -> 2 CTAs/SM

__global__ __launch_bounds__(256, 2)
void attnv_kernel(const float* __restrict__ A)
{
    extern __shared__ float sm[];
    float* sA = sm;                  // 128 x 132 raw
    float* sV = sA + 128 * 132;      // 128 x 72 raw
    const uint32_t sAa = smem_u32(sA), sVa = smem_u32(sV);

    const int tid = threadIdx.x;
    const int bh = blockIdx.y, q0 = blockIdx.x * 128;
    const int w = tid >> 5, lane = tid & 31;
    const int g = lane >> 2, t4 = lane & 3;
    const int lr = tid >> 1;
    const int lcb  = (tid & 1) * 32;   // V loader col base
    const int lcb2 = (tid & 1) * 64;   // A loader col base

    float acc[8][4];
#pragma unroll
    for (int i = 0; i < 8; i++)
#pragma unroll
        for (int j = 0; j < 4; j++) acc[i][j] = 0.f;

    for (int kt = 0; kt < 16; kt++) {
        const float* as = A + ((size_t)(bh * N_SEQ + q0 + lr)) * N_SEQ + kt * 128 + lcb2;
        const float* vs = g_V + ((size_t)bh * N_SEQ + kt * 128 + lr) * 64 + lcb;
#pragma unroll
        for (int i = 0; i < 16; i++)
            cp16(sAa + (lr * 132 + lcb2 + i * 4) * 4, as + i * 4);
#pragma unroll
        for (int i = 0; i < 8; i++)
            cp16(sVa + (lr * 72 + lcb + i * 4) * 4, vs + i * 4);
        CP_COMMIT();
        CP_WAIT0();
        __syncthreads();

#pragma unroll
        for (int kf = 0; kf < 16; kf++) {
            uint32_t ah[4], al[4];
            lda_hl(ah, al, sA + (w * 16 + g) * 132 + kf * 8 + t4, 132);
#pragma unroll
            for (int nf = 0; nf < 8; nf++) {
                // B = V^T: b0 = V[kf*8+t4][nf*8+g], b1 = same +4 rows of k
                const int bo = (kf * 8 + t4) * 72 + nf * 8 + g;
                uint32_t bh2[2], bl2[2];
                cvt_hl(sV[bo], bh2[0], bl2[0]);
                cvt_hl(sV[bo + 4 * 72], bh2[1], bl2[1]);
                mma3(acc[nf], ah, al, bh2, bl2);
            }
        }
        __syncthreads();
    }

    const int b = bh >> 3, h = bh & 7;
    float* dst0 = g_P + ((size_t)(b * N_SEQ + q0 + w * 16 + g)) * C_DIM + h * 64;
    float* dst1 = dst0 + 8 * C_DIM;
#pragma unroll
    for (int nf = 0; nf < 8; nf++) {
        const int c = nf * 8 + t4 * 2;
        *(float2*)(dst0 + c) = make_float2(acc[nf][0], acc[nf][1]);
        *(float2*)(dst1 + c) = make_float2(acc[nf][2], acc[nf][3]);
    }
}

// ---------------------------------------------------------------------------
extern "C" void kernel_launch(void* const* d_in, const int* in_sizes, int n_in,
                              void* d_out, int out_size)
{
    const float* x  = (const float*)d_in[0];
    const float* Wq = (const float*)d_in[1];
    const float* bq = (const float*)d_in[2];
    const float* Wk = (const float*)d_in[3];
    const float* bk = (const float*)d_in[4];
    const float* Wv = (const float*)d_in[5];
    const float* bv = (const float*)d_in[6];
    const float* Wo = (const float*)d_in[7];
    const float* bo = (const float*)d_in[8];

    float *dQ, *dK, *dV, *dP, *dS;
    cudaGetSymbolAddress((void**)&dQ, g_Q);
    cudaGetSymbolAddress((void**)&dK, g_K);
    cudaGetSymbolAddress((void**)&dV, g_V);
    cudaGetSymbolAddress((void**)&dP, g_P);
    cudaGetSymbolAddress((void**)&dS, g_S);

    float* out = (float*)d_out;
    const long long OUT_N = 2LL * N_SEQ * C_DIM;
    const long long ATT_N = (long long)N_BH * N_SEQ * N_SEQ;
    float* final_ptr = nullptr;
    float* attn_ptr  = nullptr;
    if ((long long)out_size >= OUT_N + ATT_N) { final_ptr = out; attn_ptr = out + OUT_N; }
    else if ((long long)out_size >= ATT_N)    { attn_ptr = out; }
    else                                      { final_ptr = out; }
    float* S = attn_ptr ? attn_ptr : dS;

    cudaFuncSetAttribute(proj_kernel,   cudaFuncAttributeMaxDynamicSharedMemorySize, PJ_SMEM);
    cudaFuncSetAttribute(scores_kernel, cudaFuncAttributeMaxDynamicSharedMemorySize, SC_SMEM);
    cudaFuncSetAttribute(attnv_kernel,  cudaFuncAttributeMaxDynamicSharedMemorySize, AV_SMEM);

    // Q, K, V projections in one launch (grid.z selects weights)
    proj_kernel<<<dim3(32, 4, 3), 256, PJ_SMEM>>>(x, Wq, Wk, Wv, bq, bk, bv,
                                                  dQ, dK, dV, 1);

    scores_kernel<<<dim3(16, 16), 256, SC_SMEM>>>(S);
    sparsemax_kernel<<<(N_BH * N_SEQ) / 8, 256>>>(S);
    attnv_kernel<<<dim3(16, 16), 256, AV_SMEM>>>(S);

    if (final_ptr)
        proj_kernel<<<dim3(32, 4, 1), 256, PJ_SMEM>>>(dP, Wo, Wo, Wo, bo, bo, bo,
                                                      final_ptr, final_ptr, final_ptr, 0);
}

// round 6
// speedup vs baseline: 1.5208x; 1.0069x over previous
#include <cuda_runtime.h>
#include <cstdint>

#define N_SEQ 2048
#define C_DIM 512
#define N_BH  16

__device__ float g_Q[N_BH * N_SEQ * 64];
__device__ float g_K[N_BH * N_SEQ * 64];
__device__ float g_V[N_BH * N_SEQ * 64];
__device__ float g_P[2 * N_SEQ * C_DIM];
__device__ float g_S[(size_t)N_BH * N_SEQ * N_SEQ];  // fallback if attn not an output

// ============================ helpers ============================
__device__ __forceinline__ uint32_t f2tf(float x) {
    uint32_t r; asm("cvt.rna.tf32.f32 %0, %1;" : "=r"(r) : "f"(x)); return r;
}
__device__ __forceinline__ uint32_t smem_u32(const void* p) {
    uint32_t a;
    asm("{ .reg .u64 t; cvta.to.shared.u64 t, %1; cvt.u32.u64 %0, t; }" : "=r"(a) : "l"(p));
    return a;
}
__device__ __forceinline__ void cp16(uint32_t s, const void* g) {
    asm volatile("cp.async.cg.shared.global [%0], [%1], 16;" :: "r"(s), "l"(g) : "memory");
}
#define CP_COMMIT() asm volatile("cp.async.commit_group;" ::: "memory")
#define CP_WAIT(n)  asm volatile("cp.async.wait_group %0;" :: "n"(n) : "memory")

__device__ __forceinline__ void mma8(float* d, const uint32_t* a, const uint32_t* b) {
    asm volatile(
        "mma.sync.aligned.m16n8k8.row.col.f32.tf32.tf32.f32 "
        "{%0,%1,%2,%3}, {%4,%5,%6,%7}, {%8,%9}, {%0,%1,%2,%3};"
        : "+f"(d[0]), "+f"(d[1]), "+f"(d[2]), "+f"(d[3])
        : "r"(a[0]), "r"(a[1]), "r"(a[2]), "r"(a[3]), "r"(b[0]), "r"(b[1]));
}
__device__ __forceinline__ void cvt_hl(float x, uint32_t& h, uint32_t& l) {
    h = f2tf(x);
    l = f2tf(x - __uint_as_float(h));
}
__device__ __forceinline__ void lda_hl(uint32_t* h, uint32_t* l, const float* p, int st) {
    cvt_hl(p[0], h[0], l[0]);
    cvt_hl(p[8 * st], h[1], l[1]);
    cvt_hl(p[4], h[2], l[2]);
    cvt_hl(p[8 * st + 4], h[3], l[3]);
}
__device__ __forceinline__ void mma3(float* acc, const uint32_t* ah, const uint32_t* al,
                                     const uint32_t* bh, const uint32_t* bl) {
    mma8(acc, ah, bh);
    mma8(acc, al, bh);
    mma8(acc, ah, bl);
}

// ======================= projection GEMM (3xTF32, pipelined) =======================
// Y = X @ W^T + bias.  CTA: 128m x 128n, BK=32 double-buffered; 8 warps = 16m.
#define PJ_SMEM ((4 * 128 * 36) * 4)   // 73,728 B -> 2 CTAs/SM

__global__ __launch_bounds__(256, 2)
void proj_kernel(const float* __restrict__ X,
                 const float* __restrict__ W0, const float* __restrict__ W1,
                 const float* __restrict__ W2,
                 const float* __restrict__ b0, const float* __restrict__ b1,
                 const float* __restrict__ b2,
                 float* __restrict__ Y0, float* __restrict__ Y1, float* __restrict__ Y2,
                 int qkv_mode)
{
    extern __shared__ float sm[];
    float* sX[2] = { sm, sm + 128 * 36 };
    float* sW[2] = { sm + 2 * 128 * 36, sm + 3 * 128 * 36 };
    uint32_t sXa[2] = { smem_u32(sX[0]), smem_u32(sX[1]) };
    uint32_t sWa[2] = { smem_u32(sW[0]), smem_u32(sW[1]) };

    const int z = blockIdx.z;
    const float* W = (z == 0) ? W0 : (z == 1) ? W1 : W2;
    const float* bias = (z == 0) ? b0 : (z == 1) ? b1 : b2;
    float* Y = (z == 0) ? Y0 : (z == 1) ? Y1 : Y2;

    const int tid = threadIdx.x;
    const int m0 = blockIdx.x * 128, n0 = blockIdx.y * 128;
    const int w = tid >> 5, lane = tid & 31;
    const int g = lane >> 2, t4 = lane & 3;
    const int lr = tid >> 1, lcb = (tid & 1) * 16;   // 4 float4s per thread per tensor

    const float* xrow = X + (size_t)(m0 + lr) * 512 + lcb;
    const float* wrow = W + (size_t)(n0 + lr) * 512 + lcb;

    auto prefetch = [&](int kk, int buf) {
#pragma unroll
        for (int i = 0; i < 4; i++) {
            cp16(sXa[buf] + (lr * 36 + lcb + i * 4) * 4, xrow + kk + i * 4);
            cp16(sWa[buf] + (lr * 36 + lcb + i * 4) * 4, wrow + kk + i * 4);
        }
        CP_COMMIT();
    };

    float acc[16][4];
#pragma unroll
    for (int i = 0; i < 16; i++)
#pragma unroll
        for (int j = 0; j < 4; j++) acc[i][j] = 0.f;

    prefetch(0, 0);
    for (int t = 0; t < 16; t++) {
        const int buf = t & 1;
        if (t < 15) prefetch((t + 1) * 32, buf ^ 1);
        if (t < 15) CP_WAIT(1); else CP_WAIT(0);
        __syncthreads();
#pragma unroll
        for (int kf = 0; kf < 4; kf++) {
            uint32_t ah[4], al[4];
            lda_hl(ah, al, sX[buf] + (w * 16 + g) * 36 + kf * 8 + t4, 36);
#pragma unroll
            for (int nf = 0; nf < 16; nf++) {
                const int bo = (nf * 8 + g) * 36 + kf * 8 + t4;
                uint32_t bh2[2], bl2[2];
                cvt_hl(sW[buf][bo], bh2[0], bl2[0]);
                cvt_hl(sW[buf][bo + 4], bh2[1], bl2[1]);
                mma3(acc[nf], ah, al, bh2, bl2);
            }
        }
        __syncthreads();
    }

    const int m = m0 + w * 16 + g;
#pragma unroll
    for (int nf = 0; nf < 16; nf++) {
        const int j = n0 + nf * 8 + t4 * 2;
        const float bx = bias[j], by = bias[j + 1];
        float2 v0 = make_float2(acc[nf][0] + bx, acc[nf][1] + by);
        float2 v1 = make_float2(acc[nf][2] + bx, acc[nf][3] + by);
        if (qkv_mode) {
            const int b = m >> 11, n = m & 2047;
            const int h = j >> 6, d = j & 63;
            *(float2*)(Y + ((size_t)(b * 8 + h) * 2048 + n) * 64 + d) = v0;
            *(float2*)(Y + ((size_t)(b * 8 + h) * 2048 + n + 8) * 64 + d) = v1;
        } else {
            *(float2*)(Y + (size_t)m * 512 + j) = v0;
            *(float2*)(Y + (size_t)(m + 8) * 512 + j) = v1;
        }
    }
}

// ======================= scores kernel (3xTF32, pipelined) =======================
// S[q,:] = (Q K^T)/8.  CTA: (bh, 128 q) x 16 k-tiles of 128; sK double-buffered.
#define SC_SMEM ((3 * 128 * 68) * 4)   // 104,448 B -> 2 CTAs/SM

__global__ __launch_bounds__(256, 2)
void scores_kernel(float* __restrict__ S)
{
    extern __shared__ float sm[];
    float* sQ = sm;
    float* sK[2] = { sm + 128 * 68, sm + 2 * 128 * 68 };
    const uint32_t sQa = smem_u32(sQ);
    uint32_t sKa[2] = { smem_u32(sK[0]), smem_u32(sK[1]) };

    const int tid = threadIdx.x;
    const int bh = blockIdx.y, q0 = blockIdx.x * 128;
    const int w = tid >> 5, lane = tid & 31;
    const int g = lane >> 2, t4 = lane & 3;
    const int lr = tid >> 1, lcb = (tid & 1) * 32;

    {   // Q tile (raw; 1/8 scale in epilogue)
        const float* qs = g_Q + ((size_t)bh * N_SEQ + q0 + lr) * 64 + lcb;
#pragma unroll
        for (int i = 0; i < 8; i++)
            cp16(sQa + (lr * 68 + lcb + i * 4) * 4, qs + i * 4);
        CP_COMMIT();
    }
    const float* krow = g_K + ((size_t)bh * N_SEQ + lr) * 64 + lcb;
    auto prefetchK = [&](int kt, int buf) {
#pragma unroll
        for (int i = 0; i < 8; i++)
            cp16(sKa[buf] + (lr * 68 + lcb + i * 4) * 4, krow + (size_t)kt * 128 * 64 + i * 4);
        CP_COMMIT();
    };

    prefetchK(0, 0);
    for (int kt = 0; kt < 16; kt++) {
        const int buf = kt & 1;
        if (kt < 15) prefetchK(kt + 1, buf ^ 1);
        if (kt < 15) CP_WAIT(1); else CP_WAIT(0);
        __syncthreads();

        float acc[16][4];
#pragma unroll
        for (int i = 0; i < 16; i++)
#pragma unroll
            for (int j = 0; j < 4; j++) acc[i][j] = 0.f;

#pragma unroll
        for (int kf = 0; kf < 8; kf++) {
            uint32_t ah[4], al[4];
            lda_hl(ah, al, sQ + (w * 16 + g) * 68 + kf * 8 + t4, 68);
#pragma unroll
            for (int nf = 0; nf < 16; nf++) {
                const int bo = (nf * 8 + g) * 68 + kf * 8 + t4;
                uint32_t bh2[2], bl2[2];
                cvt_hl(sK[buf][bo], bh2[0], bl2[0]);
                cvt_hl(sK[buf][bo + 4], bh2[1], bl2[1]);
                mma3(acc[nf], ah, al, bh2, bl2);
            }
        }

        float* dst0 = S + ((size_t)(bh * N_SEQ + q0 + w * 16 + g)) * N_SEQ + kt * 128;
        float* dst1 = dst0 + 8 * N_SEQ;
#pragma unroll
        for (int nf = 0; nf < 16; nf++) {
            const int c = nf * 8 + t4 * 2;
            *(float2*)(dst0 + c) = make_float2(acc[nf][0] * 0.125f, acc[nf][1] * 0.125f);
            *(float2*)(dst1 + c) = make_float2(acc[nf][2] * 0.125f, acc[nf][3] * 0.125f);
        }
        __syncthreads();
    }
}

// ======================= sparsemax kernel =======================
__global__ __launch_bounds__(256)
void sparsemax_kernel(float* __restrict__ A)
{
    const int lane = threadIdx.x & 31;
    const size_t row = (size_t)blockIdx.x * 8 + (threadIdx.x >> 5);
    float4* r = (float4*)(A + row * N_SEQ);
    float4 v[16];
#pragma unroll
    for (int i = 0; i < 16; i++) v[i] = r[i * 32 + lane];

    float m = -3.402823466e38f;
#pragma unroll
    for (int i = 0; i < 16; i++)
        m = fmaxf(m, fmaxf(fmaxf(v[i].x, v[i].y), fmaxf(v[i].z, v[i].w)));
#pragma unroll
    for (int o = 16; o; o >>= 1) m = fmaxf(m, __shfl_xor_sync(0xffffffffu, m, o));

    // Newton on f(tau)=sum relu(s-tau)-1: exact sparsemax threshold.
    float tau = m - 1.0f;
    for (int it = 0; it < 64; ++it) {
        float Ss = 0.f; int cnt = 0;
#pragma unroll
        for (int i = 0; i < 16; i++) {
            float d;
            d = v[i].x - tau; if (d > 0.f) { Ss += d; cnt++; }
            d = v[i].y - tau; if (d > 0.f) { Ss += d; cnt++; }
            d = v[i].z - tau; if (d > 0.f) { Ss += d; cnt++; }
            d = v[i].w - tau; if (d > 0.f) { Ss += d; cnt++; }
        }
#pragma unroll
        for (int o = 16; o; o >>= 1) {
            Ss  += __shfl_xor_sync(0xffffffffu, Ss, o);
            cnt += __shfl_xor_sync(0xffffffffu, cnt, o);
        }
        if (cnt == 0) break;
        const float delta = (Ss - 1.0f) / (float)cnt;
        tau += delta;
        if (fabsf(delta) < 1e-8f) break;
    }
#pragma unroll
    for (int i = 0; i < 16; i++) {
        float4 o;
        o.x = fmaxf(v[i].x - tau, 0.f); o.y = fmaxf(v[i].y - tau, 0.f);
        o.z = fmaxf(v[i].z - tau, 0.f); o.w = fmaxf(v[i].w - tau, 0.f);
        r[i * 32 + lane] = o;
    }
}

// ======================= attn@V kernel (3xTF32, pipelined) =======================
// P[q,d] = sum_k attn[q,k] V[k,d].  CTA: (bh, 128 q), 32 k-tiles of 64,
// double-buffered; acc in registers across whole k loop (warp = 16q x 64d).
#define AV_SMEM ((2 * (128 * 68 + 64 * 72)) * 4)   // 106,496 B -> 2 CTAs/SM

__global__ __launch_bounds__(256, 2)
void attnv_kernel(const float* __restrict__ A)
{
    extern __shared__ float sm[];
    float* sA[2] = { sm, sm + 128 * 68 };
    float* sV[2] = { sm + 2 * 128 * 68, sm + 2 * 128 * 68 + 64 * 72 };
    uint32_t sAa[2] = { smem_u32(sA[0]), smem_u32(sA[1]) };
    uint32_t sVa[2] = { smem_u32(sV[0]), smem_u32(sV[1]) };

    const int tid = threadIdx.x;
    const int bh = blockIdx.y, q0 = blockIdx.x * 128;
    const int w = tid >> 5, lane = tid & 31;
    const int g = lane >> 2, t4 = lane & 3;
    const int lrA = tid >> 1, lcA = (tid & 1) * 32;   // A: 128 rows x 64 cols
    const int lrV = tid >> 2, lcV = (tid & 3) * 16;   // V: 64 rows x 64 cols

    const float* arow = A + ((size_t)(bh * N_SEQ + q0 + lrA)) * N_SEQ + lcA;
    const float* vrow = g_V + ((size_t)bh * N_SEQ + lrV) * 64 + lcV;

    auto prefetch = [&](int kt, int buf) {
#pragma unroll
        for (int i = 0; i < 8; i++)
            cp16(sAa[buf] + (lrA * 68 + lcA + i * 4) * 4, arow + kt * 64 + i * 4);
#pragma unroll
        for (int i = 0; i < 4; i++)
            cp16(sVa[buf] + (lrV * 72 + lcV + i * 4) * 4, vrow + (size_t)kt * 64 * 64 + i * 4);
        CP_COMMIT();
    };

    float acc[8][4];
#pragma unroll
    for (int i = 0; i < 8; i++)
#pragma unroll
        for (int j = 0; j < 4; j++) acc[i][j] = 0.f;

    prefetch(0, 0);
    for (int kt = 0; kt < 32; kt++) {
        const int buf = kt & 1;
        if (kt < 31) prefetch(kt + 1, buf ^ 1);
        if (kt < 31) CP_WAIT(1); else CP_WAIT(0);
        __syncthreads();

#pragma unroll
        for (int kf = 0; kf < 8; kf++) {
            uint32_t ah[4], al[4];
            lda_hl(ah, al, sA[buf] + (w * 16 + g) * 68 + kf * 8 + t4, 68);
#pragma unroll
            for (int nf = 0; nf < 8; nf++) {
                // B = V^T: b0 = V[kf*8+t4][nf*8+g], b1 = +4 k-rows
                const int bo = (kf * 8 + t4) * 72 + nf * 8 + g;
                uint32_t bh2[2], bl2[2];
                cvt_hl(sV[buf][bo], bh2[0], bl2[0]);
                cvt_hl(sV[buf][bo + 4 * 72], bh2[1], bl2[1]);
                mma3(acc[nf], ah, al, bh2, bl2);
            }
        }
        __syncthreads();
    }

    const int b = bh >> 3, h = bh & 7;
    float* dst0 = g_P + ((size_t)(b * N_SEQ + q0 + w * 16 + g)) * C_DIM + h * 64;
    float* dst1 = dst0 + 8 * C_DIM;
#pragma unroll
    for (int nf = 0; nf < 8; nf++) {
        const int c = nf * 8 + t4 * 2;
        *(float2*)(dst0 + c) = make_float2(acc[nf][0], acc[nf][1]);
        *(float2*)(dst1 + c) = make_float2(acc[nf][2], acc[nf][3]);
    }
}

// ---------------------------------------------------------------------------
extern "C" void kernel_launch(void* const* d_in, const int* in_sizes, int n_in,
                              void* d_out, int out_size)
{
    const float* x  = (const float*)d_in[0];
    const float* Wq = (const float*)d_in[1];
    const float* bq = (const float*)d_in[2];
    const float* Wk = (const float*)d_in[3];
    const float* bk = (const float*)d_in[4];
    const float* Wv = (const float*)d_in[5];
    const float* bv = (const float*)d_in[6];
    const float* Wo = (const float*)d_in[7];
    const float* bo = (const float*)d_in[8];

    float *dQ, *dK, *dV, *dP, *dS;
    cudaGetSymbolAddress((void**)&dQ, g_Q);
    cudaGetSymbolAddress((void**)&dK, g_K);
    cudaGetSymbolAddress((void**)&dV, g_V);
    cudaGetSymbolAddress((void**)&dP, g_P);
    cudaGetSymbolAddress((void**)&dS, g_S);

    float* out = (float*)d_out;
    const long long OUT_N = 2LL * N_SEQ * C_DIM;
    const long long ATT_N = (long long)N_BH * N_SEQ * N_SEQ;
    float* final_ptr = nullptr;
    float* attn_ptr  = nullptr;
    if ((long long)out_size >= OUT_N + ATT_N) { final_ptr = out; attn_ptr = out + OUT_N; }
    else if ((long long)out_size >= ATT_N)    { attn_ptr = out; }
    else                                      { final_ptr = out; }
    float* S = attn_ptr ? attn_ptr : dS;

    cudaFuncSetAttribute(proj_kernel,   cudaFuncAttributeMaxDynamicSharedMemorySize, PJ_SMEM);
    cudaFuncSetAttribute(scores_kernel, cudaFuncAttributeMaxDynamicSharedMemorySize, SC_SMEM);
    cudaFuncSetAttribute(attnv_kernel,  cudaFuncAttributeMaxDynamicSharedMemorySize, AV_SMEM);

    proj_kernel<<<dim3(32, 4, 3), 256, PJ_SMEM>>>(x, Wq, Wk, Wv, bq, bk, bv,
                                                  dQ, dK, dV, 1);

    scores_kernel<<<dim3(16, 16), 256, SC_SMEM>>>(S);
    sparsemax_kernel<<<(N_BH * N_SEQ) / 8, 256>>>(S);
    attnv_kernel<<<dim3(16, 16), 256, AV_SMEM>>>(S);

    if (final_ptr)
        proj_kernel<<<dim3(32, 4, 1), 256, PJ_SMEM>>>(dP, Wo, Wo, Wo, bo, bo, bo,
                                                      final_ptr, final_ptr, final_ptr, 0);
}

// round 7
// speedup vs baseline: 1.5991x; 1.0515x over previous
#include <cuda_runtime.h>
#include <cstdint>

#define N_SEQ 2048
#define C_DIM 512
#define N_BH  16

// ---- device-global scratch (no allocation allowed) ----
__device__ float g_Q  [N_BH * N_SEQ * 64];          // raw Q [bh][n][d]
__device__ float g_Kh [N_BH * N_SEQ * 64];          // K hi  [bh][n][d'] (d perm8)
__device__ float g_Kl [N_BH * N_SEQ * 64];          // K lo
__device__ float g_Vth[N_BH * 64 * N_SEQ];          // V^T hi [bh][d][n'] (n perm8)
__device__ float g_Vtl[N_BH * 64 * N_SEQ];          // V^T lo
__device__ float g_P  [2 * N_SEQ * C_DIM];
__device__ float g_S  [(size_t)N_BH * N_SEQ * N_SEQ];
__device__ float g_Wph[4 * C_DIM * C_DIM];          // W hi [mat][n][c'] (c perm8)
__device__ float g_Wpl[4 * C_DIM * C_DIM];          // W lo

// ============================ helpers ============================
__device__ __forceinline__ uint32_t f2tf(float x) {
    uint32_t r; asm("cvt.rna.tf32.f32 %0, %1;" : "=r"(r) : "f"(x)); return r;
}
__device__ __forceinline__ uint32_t smem_u32(const void* p) {
    uint32_t a;
    asm("{ .reg .u64 t; cvta.to.shared.u64 t, %1; cvt.u32.u64 %0, t; }" : "=r"(a) : "l"(p));
    return a;
}
__device__ __forceinline__ void cp16(uint32_t s, const void* g) {
    asm volatile("cp.async.cg.shared.global [%0], [%1], 16;" :: "r"(s), "l"(g) : "memory");
}
#define CP_COMMIT() asm volatile("cp.async.commit_group;" ::: "memory")
#define CP_WAIT(n)  asm volatile("cp.async.wait_group %0;" :: "n"(n) : "memory")

__device__ __forceinline__ void mma8(float* d, const uint32_t* a, const uint32_t* b) {
    asm volatile(
        "mma.sync.aligned.m16n8k8.row.col.f32.tf32.tf32.f32 "
        "{%0,%1,%2,%3}, {%4,%5,%6,%7}, {%8,%9}, {%0,%1,%2,%3};"
        : "+f"(d[0]), "+f"(d[1]), "+f"(d[2]), "+f"(d[3])
        : "r"(a[0]), "r"(a[1]), "r"(a[2]), "r"(a[3]), "r"(b[0]), "r"(b[1]));
}
__device__ __forceinline__ void cvt_hl(float x, uint32_t& h, uint32_t& l) {
    h = f2tf(x);
    l = f2tf(x - __uint_as_float(h));
}
// raw A fragment from smem + in-register hi/lo split
__device__ __forceinline__ void lda_hl(uint32_t* h, uint32_t* l, const float* p, int st) {
    cvt_hl(p[0], h[0], l[0]);
    cvt_hl(p[8 * st], h[1], l[1]);
    cvt_hl(p[4], h[2], l[2]);
    cvt_hl(p[8 * st + 4], h[3], l[3]);
}
__device__ __forceinline__ void mma3(float* acc, const uint32_t* ah, const uint32_t* al,
                                     const uint32_t* bh, const uint32_t* bl) {
    mma8(acc, ah, bh);
    mma8(acc, al, bh);
    mma8(acc, ah, bl);
}
// pair-permutation within 8-groups: (k, k+4) stored adjacently
__device__ __forceinline__ int perm8(int c) {
    return (c & ~7) | ((c & 3) << 1) | ((c >> 2) & 1);
}

// =================== weight pre-split (hi/lo, c-permuted) ===================
__global__ void wconv_kernel(const float* __restrict__ W0, const float* __restrict__ W1,
                             const float* __restrict__ W2, const float* __restrict__ W3)
{
    const int mat = blockIdx.y;
    const float* W = (mat == 0) ? W0 : (mat == 1) ? W1 : (mat == 2) ? W2 : W3;
    const int n = blockIdx.x;
    for (int c = threadIdx.x; c < C_DIM; c += blockDim.x) {
        float v = W[n * C_DIM + c];
        uint32_t h, l; cvt_hl(v, h, l);
        const int cp = perm8(c);
        g_Wph[((size_t)mat * C_DIM + n) * C_DIM + cp] = __uint_as_float(h);
        g_Wpl[((size_t)mat * C_DIM + n) * C_DIM + cp] = __uint_as_float(l);
    }
}

// ======================= projection GEMM (3xTF32) =======================
// Y = X @ W^T + bias.  CTA: 128m x 64n, BK=32 double-buffered; 8 warps = 16m.
// z: 0=Q raw scatter, 1=K hi/lo (d-perm), 2=V^T hi/lo (token-perm), 3=flat out.
#define PJ_SMEM ((2 * 128 * 36 + 4 * 64 * 40) * 4)   // 77,824 B -> 2 CTAs/SM

__global__ __launch_bounds__(256, 2)
void proj_kernel(const float* __restrict__ X,
                 const float* __restrict__ b0, const float* __restrict__ b1,
                 const float* __restrict__ b2, const float* __restrict__ b3,
                 float* __restrict__ out_final, int zbase)
{
    extern __shared__ float sm[];
    float* sX[2]  = { sm, sm + 128 * 36 };
    float* sWh[2] = { sm + 2 * 128 * 36,               sm + 2 * 128 * 36 + 64 * 40 };
    float* sWl[2] = { sm + 2 * 128 * 36 + 2 * 64 * 40, sm + 2 * 128 * 36 + 3 * 64 * 40 };
    uint32_t sXa[2]  = { smem_u32(sX[0]),  smem_u32(sX[1]) };
    uint32_t sWha[2] = { smem_u32(sWh[0]), smem_u32(sWh[1]) };
    uint32_t sWla[2] = { smem_u32(sWl[0]), smem_u32(sWl[1]) };

    const int z = zbase + blockIdx.z;
    const float* bias = (z == 0) ? b0 : (z == 1) ? b1 : (z == 2) ? b2 : b3;
    const float* Wh = g_Wph + (size_t)z * C_DIM * C_DIM;
    const float* Wl = g_Wpl + (size_t)z * C_DIM * C_DIM;

    const int tid = threadIdx.x;
    const int m0 = blockIdx.x * 128, n0 = blockIdx.y * 64;
    const int w = tid >> 5, lane = tid & 31;
    const int g = lane >> 2, t4 = lane & 3;
    const int lrX = tid >> 1, lcX = (tid & 1) * 16;   // X: 128 rows x 32
    const int lrW = tid >> 2, lcW = (tid & 3) * 8;    // W: 64 rows x 32

    const float* xrow = X + (size_t)(m0 + lrX) * C_DIM + lcX;
    const float* whrow = Wh + (size_t)(n0 + lrW) * C_DIM + lcW;
    const float* wlrow = Wl + (size_t)(n0 + lrW) * C_DIM + lcW;

    auto prefetch = [&](int kk, int buf) {
#pragma unroll
        for (int i = 0; i < 4; i++)
            cp16(sXa[buf] + (lrX * 36 + lcX + i * 4) * 4, xrow + kk + i * 4);
#pragma unroll
        for (int i = 0; i < 2; i++) {
            cp16(sWha[buf] + (lrW * 40 + lcW + i * 4) * 4, whrow + kk + i * 4);
            cp16(sWla[buf] + (lrW * 40 + lcW + i * 4) * 4, wlrow + kk + i * 4);
        }
        CP_COMMIT();
    };

    float acc[8][4];
#pragma unroll
    for (int i = 0; i < 8; i++)
#pragma unroll
        for (int j = 0; j < 4; j++) acc[i][j] = 0.f;

    prefetch(0, 0);
    for (int t = 0; t < 16; t++) {
        const int buf = t & 1;
        if (t < 15) { prefetch((t + 1) * 32, buf ^ 1); CP_WAIT(1); }
        else        { CP_WAIT(0); }
        __syncthreads();
#pragma unroll
        for (int kf = 0; kf < 4; kf++) {
            uint32_t ah[4], al[4];
            lda_hl(ah, al, sX[buf] + (w * 16 + g) * 36 + kf * 8 + t4, 36);
#pragma unroll
            for (int nf = 0; nf < 8; nf++) {
                const int bo = (nf * 8 + g) * 40 + kf * 8 + t4 * 2;
                float2 h2 = *(const float2*)&sWh[buf][bo];
                float2 l2 = *(const float2*)&sWl[buf][bo];
                uint32_t bh2[2] = { __float_as_uint(h2.x), __float_as_uint(h2.y) };
                uint32_t bl2[2] = { __float_as_uint(l2.x), __float_as_uint(l2.y) };
                mma3(acc[nf], ah, al, bh2, bl2);
            }
        }
        __syncthreads();
    }

    const int m = m0 + w * 16 + g;
#pragma unroll
    for (int nf = 0; nf < 8; nf++) {
        const int j = n0 + nf * 8 + t4 * 2;
        const float bx = bias[j], by = bias[j + 1];
        float v0 = acc[nf][0] + bx, v1 = acc[nf][1] + by;   // row m
        float v2 = acc[nf][2] + bx, v3 = acc[nf][3] + by;   // row m+8
        if (z == 3) {
            *(float2*)(out_final + (size_t)m * C_DIM + j)       = make_float2(v0, v1);
            *(float2*)(out_final + (size_t)(m + 8) * C_DIM + j) = make_float2(v2, v3);
        } else {
            const int b = m >> 11, n = m & 2047;
            const int h = j >> 6, d0 = j & 63;
            const int bh = b * 8 + h;
            if (z == 0) {
                *(float2*)(g_Q + ((size_t)bh * N_SEQ + n) * 64 + d0)     = make_float2(v0, v1);
                *(float2*)(g_Q + ((size_t)bh * N_SEQ + n + 8) * 64 + d0) = make_float2(v2, v3);
            } else if (z == 1) {
                // K hi/lo, d permuted so (d, d+4) pairs are adjacent
                const int s0  = (t4 & 1) * 4 + (t4 >> 1);
                const int dp0 = (d0 & ~7) + s0, dp1 = dp0 + 2;
                const size_t r0 = ((size_t)bh * N_SEQ + n) * 64;
                const size_t r1 = r0 + 8 * 64;
                uint32_t hh, ll;
                cvt_hl(v0, hh, ll); g_Kh[r0 + dp0] = __uint_as_float(hh); g_Kl[r0 + dp0] = __uint_as_float(ll);
                cvt_hl(v1, hh, ll); g_Kh[r0 + dp1] = __uint_as_float(hh); g_Kl[r0 + dp1] = __uint_as_float(ll);
                cvt_hl(v2, hh, ll); g_Kh[r1 + dp0] = __uint_as_float(hh); g_Kl[r1 + dp0] = __uint_as_float(ll);
                cvt_hl(v3, hh, ll); g_Kh[r1 + dp1] = __uint_as_float(hh); g_Kl[r1 + dp1] = __uint_as_float(ll);
            } else {
                // V^T hi/lo: [bh][d][token'], token permuted (n%8 == g)
                const int sg = ((g & 3) << 1) | (g >> 2);
                const int np = (n & ~7) + sg;     // token n stored position
                const size_t bd = (size_t)bh * 64;
                uint32_t hh, ll;
                cvt_hl(v0, hh, ll); g_Vth[(bd + d0)     * N_SEQ + np]     = __uint_as_float(hh); g_Vtl[(bd + d0)     * N_SEQ + np]     = __uint_as_float(ll);
                cvt_hl(v1, hh, ll); g_Vth[(bd + d0 + 1) * N_SEQ + np]     = __uint_as_float(hh); g_Vtl[(bd + d0 + 1) * N_SEQ + np]     = __uint_as_float(ll);
                cvt_hl(v2, hh, ll); g_Vth[(bd + d0)     * N_SEQ + np + 8] = __uint_as_float(hh); g_Vtl[(bd + d0)     * N_SEQ + np + 8] = __uint_as_float(ll);
                cvt_hl(v3, hh, ll); g_Vth[(bd + d0 + 1) * N_SEQ + np + 8] = __uint_as_float(hh); g_Vtl[(bd + d0 + 1) * N_SEQ + np + 8] = __uint_as_float(ll);
            }
        }
    }
}

// ======================= scores kernel (3xTF32) =======================
// S[q,:] = (Q K^T)/8.  CTA: (bh, 128 q) x 32 token-tiles of 64.
// B = K hi/lo precomputed (zero cvt in loop), fragment pairs via LDS.64.
#define SC_SMEM ((128 * 68 + 4 * 64 * 72) * 4)   // 108,544 B -> 2 CTAs/SM

__global__ __launch_bounds__(256, 2)
void scores_kernel(float* __restrict__ S)
{
    extern __shared__ float sm[];
    float* sQ = sm;                                   // 128 x 68 raw
    float* sKh[2] = { sm + 128 * 68,               sm + 128 * 68 + 64 * 72 };
    float* sKl[2] = { sm + 128 * 68 + 2 * 64 * 72, sm + 128 * 68 + 3 * 64 * 72 };
    const uint32_t sQa = smem_u32(sQ);
    uint32_t sKha[2] = { smem_u32(sKh[0]), smem_u32(sKh[1]) };
    uint32_t sKla[2] = { smem_u32(sKl[0]), smem_u32(sKl[1]) };

    const int tid = threadIdx.x;
    const int bh = blockIdx.y, q0 = blockIdx.x * 128;
    const int w = tid >> 5, lane = tid & 31;
    const int g = lane >> 2, t4 = lane & 3;
    const int lrQ = tid >> 1, lcQ = (tid & 1) * 32;   // Q: 128 rows x 64
    const int lrK = tid >> 2, lcK = (tid & 3) * 16;   // K: 64 rows x 64

    {   // Q tile (raw; 1/8 scale in epilogue)
        const float* qs = g_Q + ((size_t)bh * N_SEQ + q0 + lrQ) * 64 + lcQ;
#pragma unroll
        for (int i = 0; i < 8; i++)
            cp16(sQa + (lrQ * 68 + lcQ + i * 4) * 4, qs + i * 4);
        CP_COMMIT();
    }
    const float* khrow = g_Kh + ((size_t)bh * N_SEQ + lrK) * 64 + lcK;
    const float* klrow = g_Kl + ((size_t)bh * N_SEQ + lrK) * 64 + lcK;
    auto prefetchK = [&](int kt, int buf) {
        const size_t off = (size_t)kt * 64 * 64;
#pragma unroll
        for (int i = 0; i < 4; i++) {
            cp16(sKha[buf] + (lrK * 72 + lcK + i * 4) * 4, khrow + off + i * 4);
            cp16(sKla[buf] + (lrK * 72 + lcK + i * 4) * 4, klrow + off + i * 4);
        }
        CP_COMMIT();
    };

    prefetchK(0, 0);
    for (int kt = 0; kt < 32; kt++) {
        const int buf = kt & 1;
        if (kt < 31) { prefetchK(kt + 1, buf ^ 1); CP_WAIT(1); }
        else         { CP_WAIT(0); }
        __syncthreads();

        float acc[8][4];
#pragma unroll
        for (int i = 0; i < 8; i++)
#pragma unroll
            for (int j = 0; j < 4; j++) acc[i][j] = 0.f;

#pragma unroll
        for (int kf = 0; kf < 8; kf++) {
            uint32_t ah[4], al[4];
            lda_hl(ah, al, sQ + (w * 16 + g) * 68 + kf * 8 + t4, 68);
#pragma unroll
            for (int nf = 0; nf < 8; nf++) {
                const int bo = (nf * 8 + g) * 72 + kf * 8 + t4 * 2;
                float2 h2 = *(const float2*)&sKh[buf][bo];
                float2 l2 = *(const float2*)&sKl[buf][bo];
                uint32_t bh2[2] = { __float_as_uint(h2.x), __float_as_uint(h2.y) };
                uint32_t bl2[2] = { __float_as_uint(l2.x), __float_as_uint(l2.y) };
                mma3(acc[nf], ah, al, bh2, bl2);
            }
        }

        float* dst0 = S + ((size_t)(bh * N_SEQ + q0 + w * 16 + g)) * N_SEQ + kt * 64;
        float* dst1 = dst0 + 8 * N_SEQ;
#pragma unroll
        for (int nf = 0; nf < 8; nf++) {
            const int c = nf * 8 + t4 * 2;
            *(float2*)(dst0 + c) = make_float2(acc[nf][0] * 0.125f, acc[nf][1] * 0.125f);
            *(float2*)(dst1 + c) = make_float2(acc[nf][2] * 0.125f, acc[nf][3] * 0.125f);
        }
        __syncthreads();
    }
}

// ======================= sparsemax kernel =======================
__global__ __launch_bounds__(256)
void sparsemax_kernel(float* __restrict__ A)
{
    const int lane = threadIdx.x & 31;
    const size_t row = (size_t)blockIdx.x * 8 + (threadIdx.x >> 5);
    float4* r = (float4*)(A + row * N_SEQ);
    float4 v[16];
#pragma unroll
    for (int i = 0; i < 16; i++) v[i] = r[i * 32 + lane];

    float m = -3.402823466e38f;
#pragma unroll
    for (int i = 0; i < 16; i++)
        m = fmaxf(m, fmaxf(fmaxf(v[i].x, v[i].y), fmaxf(v[i].z, v[i].w)));
#pragma unroll
    for (int o = 16; o; o >>= 1) m = fmaxf(m, __shfl_xor_sync(0xffffffffu, m, o));

    // Newton on f(tau)=sum relu(s-tau)-1: exact sparsemax threshold.
    float tau = m - 1.0f;
    for (int it = 0; it < 64; ++it) {
        float Ss = 0.f; int cnt = 0;
#pragma unroll
        for (int i = 0; i < 16; i++) {
            float d;
            d = v[i].x - tau; if (d > 0.f) { Ss += d; cnt++; }
            d = v[i].y - tau; if (d > 0.f) { Ss += d; cnt++; }
            d = v[i].z - tau; if (d > 0.f) { Ss += d; cnt++; }
            d = v[i].w - tau; if (d > 0.f) { Ss += d; cnt++; }
        }
#pragma unroll
        for (int o = 16; o; o >>= 1) {
            Ss  += __shfl_xor_sync(0xffffffffu, Ss, o);
            cnt += __shfl_xor_sync(0xffffffffu, cnt, o);
        }
        if (cnt == 0) break;
        const float delta = (Ss - 1.0f) / (float)cnt;
        tau += delta;
        if (fabsf(delta) < 1e-8f) break;
    }
#pragma unroll
    for (int i = 0; i < 16; i++) {
        float4 o;
        o.x = fmaxf(v[i].x - tau, 0.f); o.y = fmaxf(v[i].y - tau, 0.f);
        o.z = fmaxf(v[i].z - tau, 0.f); o.w = fmaxf(v[i].w - tau, 0.f);
        r[i * 32 + lane] = o;
    }
}

// ======================= attn@V kernel (3xTF32) =======================
// P[q,d] = sum_k attn[q,k] V[k,d].  CTA: (bh, 128 q), 64 token-tiles of 32.
// B = V^T hi/lo precomputed (token-permuted), LDS.64 pairs; A raw in-reg cvt.
#define AV_SMEM ((2 * 128 * 36 + 4 * 64 * 40) * 4)   // 77,824 B -> 2 CTAs/SM

__global__ __launch_bounds__(256, 2)
void attnv_kernel(const float* __restrict__ A)
{
    extern __shared__ float sm[];
    float* sA[2]  = { sm, sm + 128 * 36 };
    float* sVh[2] = { sm + 2 * 128 * 36,               sm + 2 * 128 * 36 + 64 * 40 };
    float* sVl[2] = { sm + 2 * 128 * 36 + 2 * 64 * 40, sm + 2 * 128 * 36 + 3 * 64 * 40 };
    uint32_t sAa[2]  = { smem_u32(sA[0]),  smem_u32(sA[1]) };
    uint32_t sVha[2] = { smem_u32(sVh[0]), smem_u32(sVh[1]) };
    uint32_t sVla[2] = { smem_u32(sVl[0]), smem_u32(sVl[1]) };

    const int tid = threadIdx.x;
    const int bh = blockIdx.y, q0 = blockIdx.x * 128;
    const int w = tid >> 5, lane = tid & 31;
    const int g = lane >> 2, t4 = lane & 3;
    const int lrA = tid >> 1, lcA = (tid & 1) * 16;   // A: 128 rows x 32
    const int lrV = tid >> 2, lcV = (tid & 3) * 8;    // V^T: 64 d-rows x 32

    const float* arow  = A + ((size_t)(bh * N_SEQ + q0 + lrA)) * N_SEQ + lcA;
    const float* vhrow = g_Vth + ((size_t)bh * 64 + lrV) * N_SEQ + lcV;
    const float* vlrow = g_Vtl + ((size_t)bh * 64 + lrV) * N_SEQ + lcV;

    auto prefetch = [&](int kt, int buf) {
        const int off = kt * 32;
#pragma unroll
        for (int i = 0; i < 4; i++)
            cp16(sAa[buf] + (lrA * 36 + lcA + i * 4) * 4, arow + off + i * 4);
#pragma unroll
        for (int i = 0; i < 2; i++) {
            cp16(sVha[buf] + (lrV * 40 + lcV + i * 4) * 4, vhrow + off + i * 4);
            cp16(sVla[buf] + (lrV * 40 + lcV + i * 4) * 4, vlrow + off + i * 4);
        }
        CP_COMMIT();
    };

    float acc[8][4];
#pragma unroll
    for (int i = 0; i < 8; i++)
#pragma unroll
        for (int j = 0; j < 4; j++) acc[i][j] = 0.f;

    prefetch(0, 0);
    for (int kt = 0; kt < 64; kt++) {
        const int buf = kt & 1;
        if (kt < 63) { prefetch(kt + 1, buf ^ 1); CP_WAIT(1); }
        else         { CP_WAIT(0); }
        __syncthreads();

#pragma unroll
        for (int kf = 0; kf < 4; kf++) {
            uint32_t ah[4], al[4];
            lda_hl(ah, al, sA[buf] + (w * 16 + g) * 36 + kf * 8 + t4, 36);
#pragma unroll
            for (int nf = 0; nf < 8; nf++) {
                const int bo = (nf * 8 + g) * 40 + kf * 8 + t4 * 2;
                float2 h2 = *(const float2*)&sVh[buf][bo];
                float2 l2 = *(const float2*)&sVl[buf][bo];
                uint32_t bh2[2] = { __float_as_uint(h2.x), __float_as_uint(h2.y) };
                uint32_t bl2[2] = { __float_as_uint(l2.x), __float_as_uint(l2.y) };
                mma3(acc[nf], ah, al, bh2, bl2);
            }
        }
        __syncthreads();
    }

    const int b = bh >> 3, h = bh & 7;
    float* dst0 = g_P + ((size_t)(b * N_SEQ + q0 + w * 16 + g)) * C_DIM + h * 64;
    float* dst1 = dst0 + 8 * C_DIM;
#pragma unroll
    for (int nf = 0; nf < 8; nf++) {
        const int c = nf * 8 + t4 * 2;
        *(float2*)(dst0 + c) = make_float2(acc[nf][0], acc[nf][1]);
        *(float2*)(dst1 + c) = make_float2(acc[nf][2], acc[nf][3]);
    }
}

// ---------------------------------------------------------------------------
extern "C" void kernel_launch(void* const* d_in, const int* in_sizes, int n_in,
                              void* d_out, int out_size)
{
    const float* x  = (const float*)d_in[0];
    const float* Wq = (const float*)d_in[1];
    const float* bq = (const float*)d_in[2];
    const float* Wk = (const float*)d_in[3];
    const float* bk = (const float*)d_in[4];
    const float* Wv = (const float*)d_in[5];
    const float* bv = (const float*)d_in[6];
    const float* Wo = (const float*)d_in[7];
    const float* bo = (const float*)d_in[8];

    float *dP, *dS;
    cudaGetSymbolAddress((void**)&dP, g_P);
    cudaGetSymbolAddress((void**)&dS, g_S);

    float* out = (float*)d_out;
    const long long OUT_N = 2LL * N_SEQ * C_DIM;
    const long long ATT_N = (long long)N_BH * N_SEQ * N_SEQ;
    float* final_ptr = nullptr;
    float* attn_ptr  = nullptr;
    if ((long long)out_size >= OUT_N + ATT_N) { final_ptr = out; attn_ptr = out + OUT_N; }
    else if ((long long)out_size >= ATT_N)    { attn_ptr = out; }
    else                                      { final_ptr = out; }
    float* S = attn_ptr ? attn_ptr : dS;

    cudaFuncSetAttribute(proj_kernel,   cudaFuncAttributeMaxDynamicSharedMemorySize, PJ_SMEM);
    cudaFuncSetAttribute(scores_kernel, cudaFuncAttributeMaxDynamicSharedMemorySize, SC_SMEM);
    cudaFuncSetAttribute(attnv_kernel,  cudaFuncAttributeMaxDynamicSharedMemorySize, AV_SMEM);

    // pre-split weights into hi/lo (c-permuted); mats: 0=Wq 1=Wk 2=Wv 3=Wo
    wconv_kernel<<<dim3(C_DIM, 4), 128>>>(Wq, Wk, Wv, Wo);

    // Q/K/V projections in one launch (z selects weight + epilogue format)
    proj_kernel<<<dim3(32, 8, 3), 256, PJ_SMEM>>>(x, bq, bk, bv, bo, nullptr, 0);

    scores_kernel<<<dim3(16, 16), 256, SC_SMEM>>>(S);
    sparsemax_kernel<<<(N_BH * N_SEQ) / 8, 256>>>(S);
    attnv_kernel<<<dim3(16, 16), 256, AV_SMEM>>>(S);

    if (final_ptr)
        proj_kernel<<<dim3(32, 8, 1), 256, PJ_SMEM>>>(dP, bq, bk, bv, bo, final_ptr, 3);
}

// round 8
// speedup vs baseline: 2.2249x; 1.3913x over previous
#include <cuda_runtime.h>
#include <cstdint>

#define N_SEQ 2048
#define C_DIM 512
#define N_BH  16

// ---- device-global scratch (no allocation allowed) ----
__device__ float g_Q  [N_BH * N_SEQ * 64];          // raw Q [bh][n][d]
__device__ float g_Kh [N_BH * N_SEQ * 64];          // K hi  [bh][n][d'] (d perm8)
__device__ float g_Kl [N_BH * N_SEQ * 64];          // K lo
__device__ float g_Vth[N_BH * 64 * N_SEQ];          // V^T hi [bh][d][n'] (n perm8)
__device__ float g_Vtl[N_BH * 64 * N_SEQ];          // V^T lo
__device__ float g_P  [2 * N_SEQ * C_DIM];
__device__ float g_S  [(size_t)N_BH * N_SEQ * N_SEQ];
__device__ float g_Wph[4 * C_DIM * C_DIM];          // W hi [mat][n][c'] (c perm8)
__device__ float g_Wpl[4 * C_DIM * C_DIM];          // W lo

// ============================ helpers ============================
__device__ __forceinline__ uint32_t f2tf(float x) {
    uint32_t r; asm("cvt.rna.tf32.f32 %0, %1;" : "=r"(r) : "f"(x)); return r;
}
__device__ __forceinline__ uint32_t smem_u32(const void* p) {
    uint32_t a;
    asm("{ .reg .u64 t; cvta.to.shared.u64 t, %1; cvt.u32.u64 %0, t; }" : "=r"(a) : "l"(p));
    return a;
}
__device__ __forceinline__ void cp16(uint32_t s, const void* g) {
    asm volatile("cp.async.cg.shared.global [%0], [%1], 16;" :: "r"(s), "l"(g) : "memory");
}
#define CP_COMMIT() asm volatile("cp.async.commit_group;" ::: "memory")
#define CP_WAIT(n)  asm volatile("cp.async.wait_group %0;" :: "n"(n) : "memory")

__device__ __forceinline__ void mma8(float* d, const uint32_t* a, const uint32_t* b) {
    asm volatile(
        "mma.sync.aligned.m16n8k8.row.col.f32.tf32.tf32.f32 "
        "{%0,%1,%2,%3}, {%4,%5,%6,%7}, {%8,%9}, {%0,%1,%2,%3};"
        : "+f"(d[0]), "+f"(d[1]), "+f"(d[2]), "+f"(d[3])
        : "r"(a[0]), "r"(a[1]), "r"(a[2]), "r"(a[3]), "r"(b[0]), "r"(b[1]));
}
__device__ __forceinline__ void cvt_hl(float x, uint32_t& h, uint32_t& l) {
    h = f2tf(x);
    l = f2tf(x - __uint_as_float(h));
}
// raw A fragment from smem + in-register hi/lo split
__device__ __forceinline__ void lda_hl(uint32_t* h, uint32_t* l, const float* p, int st) {
    cvt_hl(p[0], h[0], l[0]);
    cvt_hl(p[8 * st], h[1], l[1]);
    cvt_hl(p[4], h[2], l[2]);
    cvt_hl(p[8 * st + 4], h[3], l[3]);
}
__device__ __forceinline__ void mma3(float* acc, const uint32_t* ah, const uint32_t* al,
                                     const uint32_t* bh, const uint32_t* bl) {
    mma8(acc, ah, bh);
    mma8(acc, al, bh);
    mma8(acc, ah, bl);
}
// pair-permutation within 8-groups: (k, k+4) stored adjacently
__device__ __forceinline__ int perm8(int c) {
    return (c & ~7) | ((c & 3) << 1) | ((c >> 2) & 1);
}

// =================== weight pre-split (hi/lo, c-permuted) ===================
__global__ void wconv_kernel(const float* __restrict__ W0, const float* __restrict__ W1,
                             const float* __restrict__ W2, const float* __restrict__ W3)
{
    const int mat = blockIdx.y;
    const float* W = (mat == 0) ? W0 : (mat == 1) ? W1 : (mat == 2) ? W2 : W3;
    const int n = blockIdx.x;
    for (int c = threadIdx.x; c < C_DIM; c += blockDim.x) {
        float v = W[n * C_DIM + c];
        uint32_t h, l; cvt_hl(v, h, l);
        const int cp = perm8(c);
        g_Wph[((size_t)mat * C_DIM + n) * C_DIM + cp] = __uint_as_float(h);
        g_Wpl[((size_t)mat * C_DIM + n) * C_DIM + cp] = __uint_as_float(l);
    }
}

// ======================= projection GEMM (3xTF32) =======================
// Y = X @ W^T + bias.  CTA: 128m x 64n, BK=32 double-buffered; 8 warps = 16m.
// z: 0=Q raw scatter, 1=K hi/lo (d-perm), 2=V^T hi/lo (token-perm), 3=flat out.
#define PJ_SMEM ((2 * 128 * 36 + 4 * 64 * 40) * 4)   // 77,824 B -> 2 CTAs/SM

__global__ __launch_bounds__(256, 2)
void proj_kernel(const float* __restrict__ X,
                 const float* __restrict__ b0, const float* __restrict__ b1,
                 const float* __restrict__ b2, const float* __restrict__ b3,
                 float* __restrict__ out_final, int zbase)
{
    extern __shared__ float sm[];
    float* sX[2]  = { sm, sm + 128 * 36 };
    float* sWh[2] = { sm + 2 * 128 * 36,               sm + 2 * 128 * 36 + 64 * 40 };
    float* sWl[2] = { sm + 2 * 128 * 36 + 2 * 64 * 40, sm + 2 * 128 * 36 + 3 * 64 * 40 };
    uint32_t sXa[2]  = { smem_u32(sX[0]),  smem_u32(sX[1]) };
    uint32_t sWha[2] = { smem_u32(sWh[0]), smem_u32(sWh[1]) };
    uint32_t sWla[2] = { smem_u32(sWl[0]), smem_u32(sWl[1]) };

    const int z = zbase + blockIdx.z;
    const float* bias = (z == 0) ? b0 : (z == 1) ? b1 : (z == 2) ? b2 : b3;
    const float* Wh = g_Wph + (size_t)z * C_DIM * C_DIM;
    const float* Wl = g_Wpl + (size_t)z * C_DIM * C_DIM;

    const int tid = threadIdx.x;
    const int m0 = blockIdx.x * 128, n0 = blockIdx.y * 64;
    const int w = tid >> 5, lane = tid & 31;
    const int g = lane >> 2, t4 = lane & 3;
    const int lrX = tid >> 1, lcX = (tid & 1) * 16;   // X: 128 rows x 32
    const int lrW = tid >> 2, lcW = (tid & 3) * 8;    // W: 64 rows x 32

    const float* xrow = X + (size_t)(m0 + lrX) * C_DIM + lcX;
    const float* whrow = Wh + (size_t)(n0 + lrW) * C_DIM + lcW;
    const float* wlrow = Wl + (size_t)(n0 + lrW) * C_DIM + lcW;

    auto prefetch = [&](int kk, int buf) {
#pragma unroll
        for (int i = 0; i < 4; i++)
            cp16(sXa[buf] + (lrX * 36 + lcX + i * 4) * 4, xrow + kk + i * 4);
#pragma unroll
        for (int i = 0; i < 2; i++) {
            cp16(sWha[buf] + (lrW * 40 + lcW + i * 4) * 4, whrow + kk + i * 4);
            cp16(sWla[buf] + (lrW * 40 + lcW + i * 4) * 4, wlrow + kk + i * 4);
        }
        CP_COMMIT();
    };

    float acc[8][4];
#pragma unroll
    for (int i = 0; i < 8; i++)
#pragma unroll
        for (int j = 0; j < 4; j++) acc[i][j] = 0.f;

    prefetch(0, 0);
    for (int t = 0; t < 16; t++) {
        const int buf = t & 1;
        if (t < 15) { prefetch((t + 1) * 32, buf ^ 1); CP_WAIT(1); }
        else        { CP_WAIT(0); }
        __syncthreads();
#pragma unroll
        for (int kf = 0; kf < 4; kf++) {
            uint32_t ah[4], al[4];
            lda_hl(ah, al, sX[buf] + (w * 16 + g) * 36 + kf * 8 + t4, 36);
#pragma unroll
            for (int nf = 0; nf < 8; nf++) {
                const int bo = (nf * 8 + g) * 40 + kf * 8 + t4 * 2;
                float2 h2 = *(const float2*)&sWh[buf][bo];
                float2 l2 = *(const float2*)&sWl[buf][bo];
                uint32_t bh2[2] = { __float_as_uint(h2.x), __float_as_uint(h2.y) };
                uint32_t bl2[2] = { __float_as_uint(l2.x), __float_as_uint(l2.y) };
                mma3(acc[nf], ah, al, bh2, bl2);
            }
        }
        __syncthreads();
    }

    const int m = m0 + w * 16 + g;
#pragma unroll
    for (int nf = 0; nf < 8; nf++) {
        const int j = n0 + nf * 8 + t4 * 2;
        const float bx = bias[j], by = bias[j + 1];
        float v0 = acc[nf][0] + bx, v1 = acc[nf][1] + by;   // row m
        float v2 = acc[nf][2] + bx, v3 = acc[nf][3] + by;   // row m+8
        if (z == 3) {
            *(float2*)(out_final + (size_t)m * C_DIM + j)       = make_float2(v0, v1);
            *(float2*)(out_final + (size_t)(m + 8) * C_DIM + j) = make_float2(v2, v3);
        } else {
            const int b = m >> 11, n = m & 2047;
            const int h = j >> 6, d0 = j & 63;
            const int bh = b * 8 + h;
            if (z == 0) {
                *(float2*)(g_Q + ((size_t)bh * N_SEQ + n) * 64 + d0)     = make_float2(v0, v1);
                *(float2*)(g_Q + ((size_t)bh * N_SEQ + n + 8) * 64 + d0) = make_float2(v2, v3);
            } else if (z == 1) {
                // K hi/lo, d permuted so (d, d+4) pairs are adjacent
                const int s0  = (t4 & 1) * 4 + (t4 >> 1);
                const int dp0 = (d0 & ~7) + s0, dp1 = dp0 + 2;
                const size_t r0 = ((size_t)bh * N_SEQ + n) * 64;
                const size_t r1 = r0 + 8 * 64;
                uint32_t hh, ll;
                cvt_hl(v0, hh, ll); g_Kh[r0 + dp0] = __uint_as_float(hh); g_Kl[r0 + dp0] = __uint_as_float(ll);
                cvt_hl(v1, hh, ll); g_Kh[r0 + dp1] = __uint_as_float(hh); g_Kl[r0 + dp1] = __uint_as_float(ll);
                cvt_hl(v2, hh, ll); g_Kh[r1 + dp0] = __uint_as_float(hh); g_Kl[r1 + dp0] = __uint_as_float(ll);
                cvt_hl(v3, hh, ll); g_Kh[r1 + dp1] = __uint_as_float(hh); g_Kl[r1 + dp1] = __uint_as_float(ll);
            } else {
                // V^T hi/lo: [bh][d][token'], token permuted (n%8 == g)
                const int sg = ((g & 3) << 1) | (g >> 2);
                const int np = (n & ~7) + sg;     // token n stored position
                const size_t bd = (size_t)bh * 64;
                uint32_t hh, ll;
                cvt_hl(v0, hh, ll); g_Vth[(bd + d0)     * N_SEQ + np]     = __uint_as_float(hh); g_Vtl[(bd + d0)     * N_SEQ + np]     = __uint_as_float(ll);
                cvt_hl(v1, hh, ll); g_Vth[(bd + d0 + 1) * N_SEQ + np]     = __uint_as_float(hh); g_Vtl[(bd + d0 + 1) * N_SEQ + np]     = __uint_as_float(ll);
                cvt_hl(v2, hh, ll); g_Vth[(bd + d0)     * N_SEQ + np + 8] = __uint_as_float(hh); g_Vtl[(bd + d0)     * N_SEQ + np + 8] = __uint_as_float(ll);
                cvt_hl(v3, hh, ll); g_Vth[(bd + d0 + 1) * N_SEQ + np + 8] = __uint_as_float(hh); g_Vtl[(bd + d0 + 1) * N_SEQ + np + 8] = __uint_as_float(ll);
            }
        }
    }
}

// ======================= scores kernel (3xTF32) =======================
// S[q,:] = (Q K^T)/8.  CTA: (bh, 128 q) x 32 token-tiles of 64.
#define SC_SMEM ((128 * 68 + 4 * 64 * 72) * 4)   // 108,544 B -> 2 CTAs/SM

__global__ __launch_bounds__(256, 2)
void scores_kernel(float* __restrict__ S)
{
    extern __shared__ float sm[];
    float* sQ = sm;                                   // 128 x 68 raw
    float* sKh[2] = { sm + 128 * 68,               sm + 128 * 68 + 64 * 72 };
    float* sKl[2] = { sm + 128 * 68 + 2 * 64 * 72, sm + 128 * 68 + 3 * 64 * 72 };
    const uint32_t sQa = smem_u32(sQ);
    uint32_t sKha[2] = { smem_u32(sKh[0]), smem_u32(sKh[1]) };
    uint32_t sKla[2] = { smem_u32(sKl[0]), smem_u32(sKl[1]) };

    const int tid = threadIdx.x;
    const int bh = blockIdx.y, q0 = blockIdx.x * 128;
    const int w = tid >> 5, lane = tid & 31;
    const int g = lane >> 2, t4 = lane & 3;
    const int lrQ = tid >> 1, lcQ = (tid & 1) * 32;   // Q: 128 rows x 64
    const int lrK = tid >> 2, lcK = (tid & 3) * 16;   // K: 64 rows x 64

    {   // Q tile (raw; 1/8 scale in epilogue)
        const float* qs = g_Q + ((size_t)bh * N_SEQ + q0 + lrQ) * 64 + lcQ;
#pragma unroll
        for (int i = 0; i < 8; i++)
            cp16(sQa + (lrQ * 68 + lcQ + i * 4) * 4, qs + i * 4);
        CP_COMMIT();
    }
    const float* khrow = g_Kh + ((size_t)bh * N_SEQ + lrK) * 64 + lcK;
    const float* klrow = g_Kl + ((size_t)bh * N_SEQ + lrK) * 64 + lcK;
    auto prefetchK = [&](int kt, int buf) {
        const size_t off = (size_t)kt * 64 * 64;
#pragma unroll
        for (int i = 0; i < 4; i++) {
            cp16(sKha[buf] + (lrK * 72 + lcK + i * 4) * 4, khrow + off + i * 4);
            cp16(sKla[buf] + (lrK * 72 + lcK + i * 4) * 4, klrow + off + i * 4);
        }
        CP_COMMIT();
    };

    prefetchK(0, 0);
    for (int kt = 0; kt < 32; kt++) {
        const int buf = kt & 1;
        if (kt < 31) { prefetchK(kt + 1, buf ^ 1); CP_WAIT(1); }
        else         { CP_WAIT(0); }
        __syncthreads();

        float acc[8][4];
#pragma unroll
        for (int i = 0; i < 8; i++)
#pragma unroll
            for (int j = 0; j < 4; j++) acc[i][j] = 0.f;

#pragma unroll
        for (int kf = 0; kf < 8; kf++) {
            uint32_t ah[4], al[4];
            lda_hl(ah, al, sQ + (w * 16 + g) * 68 + kf * 8 + t4, 68);
#pragma unroll
            for (int nf = 0; nf < 8; nf++) {
                const int bo = (nf * 8 + g) * 72 + kf * 8 + t4 * 2;
                float2 h2 = *(const float2*)&sKh[buf][bo];
                float2 l2 = *(const float2*)&sKl[buf][bo];
                uint32_t bh2[2] = { __float_as_uint(h2.x), __float_as_uint(h2.y) };
                uint32_t bl2[2] = { __float_as_uint(l2.x), __float_as_uint(l2.y) };
                mma3(acc[nf], ah, al, bh2, bl2);
            }
        }

        float* dst0 = S + ((size_t)(bh * N_SEQ + q0 + w * 16 + g)) * N_SEQ + kt * 64;
        float* dst1 = dst0 + 8 * N_SEQ;
#pragma unroll
        for (int nf = 0; nf < 8; nf++) {
            const int c = nf * 8 + t4 * 2;
            *(float2*)(dst0 + c) = make_float2(acc[nf][0] * 0.125f, acc[nf][1] * 0.125f);
            *(float2*)(dst1 + c) = make_float2(acc[nf][2] * 0.125f, acc[nf][3] * 0.125f);
        }
        __syncthreads();
    }
}

// ======================= sparsemax kernel =======================
// One row per warp. Key fact: tau* >= max-1, so only elements > max-1 can be
// in the support; filter them into a tiny register buffer (select-insert keeps
// it in registers), then Newton iterates over <=8 values instead of 64.
// Warp-ballot overflow check falls back to the exact full-scan loop.
__global__ __launch_bounds__(256)
void sparsemax_kernel(float* __restrict__ A)
{
    const int lane = threadIdx.x & 31;
    const size_t row = (size_t)blockIdx.x * 8 + (threadIdx.x >> 5);
    float4* r = (float4*)(A + row * N_SEQ);
    float4 v[16];
#pragma unroll
    for (int i = 0; i < 16; i++) v[i] = r[i * 32 + lane];

    float m = -3.402823466e38f;
#pragma unroll
    for (int i = 0; i < 16; i++)
        m = fmaxf(m, fmaxf(fmaxf(v[i].x, v[i].y), fmaxf(v[i].z, v[i].w)));
#pragma unroll
    for (int o = 16; o; o >>= 1) m = fmaxf(m, __shfl_xor_sync(0xffffffffu, m, o));

    const float thr = m - 1.0f;

    // ---- collect candidates (> thr) into register buffer ----
    float cbuf[8];
#pragma unroll
    for (int j = 0; j < 8; j++) cbuf[j] = -3.402823466e38f;
    int ccnt = 0;
#pragma unroll
    for (int i = 0; i < 16; i++) {
        float e[4] = { v[i].x, v[i].y, v[i].z, v[i].w };
#pragma unroll
        for (int c = 0; c < 4; c++) {
            if (e[c] > thr) {
                if (ccnt < 8) {
#pragma unroll
                    for (int j = 0; j < 8; j++)
                        if (ccnt == j) cbuf[j] = e[c];
                }
                ccnt++;
            }
        }
    }

    float tau = thr;
    if (__ballot_sync(0xffffffffu, ccnt > 8)) {
        // exact fallback: full-scan Newton (rare)
        for (int it = 0; it < 64; ++it) {
            float Ss = 0.f; int cnt = 0;
#pragma unroll
            for (int i = 0; i < 16; i++) {
                float d;
                d = v[i].x - tau; if (d > 0.f) { Ss += d; cnt++; }
                d = v[i].y - tau; if (d > 0.f) { Ss += d; cnt++; }
                d = v[i].z - tau; if (d > 0.f) { Ss += d; cnt++; }
                d = v[i].w - tau; if (d > 0.f) { Ss += d; cnt++; }
            }
#pragma unroll
            for (int o = 16; o; o >>= 1) {
                Ss  += __shfl_xor_sync(0xffffffffu, Ss, o);
                cnt += __shfl_xor_sync(0xffffffffu, cnt, o);
            }
            if (cnt == 0) break;
            const float delta = (Ss - 1.0f) / (float)cnt;
            tau += delta;
            if (fabsf(delta) < 1e-8f) break;
        }
    } else {
        // Newton on candidate registers only (same math, same FP order)
        for (int it = 0; it < 64; ++it) {
            float Ss = 0.f; int cnt = 0;
#pragma unroll
            for (int j = 0; j < 8; j++) {
                float d = cbuf[j] - tau;
                if (j < ccnt && d > 0.f) { Ss += d; cnt++; }
            }
#pragma unroll
            for (int o = 16; o; o >>= 1) {
                Ss  += __shfl_xor_sync(0xffffffffu, Ss, o);
                cnt += __shfl_xor_sync(0xffffffffu, cnt, o);
            }
            if (cnt == 0) break;
            const float delta = (Ss - 1.0f) / (float)cnt;
            tau += delta;
            if (fabsf(delta) < 1e-8f) break;
        }
    }

#pragma unroll
    for (int i = 0; i < 16; i++) {
        float4 o;
        o.x = fmaxf(v[i].x - tau, 0.f); o.y = fmaxf(v[i].y - tau, 0.f);
        o.z = fmaxf(v[i].z - tau, 0.f); o.w = fmaxf(v[i].w - tau, 0.f);
        r[i * 32 + lane] = o;
    }
}

// ======================= attn@V kernel (3xTF32) =======================
// P[q,d] = sum_k attn[q,k] V[k,d].  CTA: (bh, 128 q), 64 token-tiles of 32.
#define AV_SMEM ((2 * 128 * 36 + 4 * 64 * 40) * 4)   // 77,824 B -> 2 CTAs/SM

__global__ __launch_bounds__(256, 2)
void attnv_kernel(const float* __restrict__ A)
{
    extern __shared__ float sm[];
    float* sA[2]  = { sm, sm + 128 * 36 };
    float* sVh[2] = { sm + 2 * 128 * 36,               sm + 2 * 128 * 36 + 64 * 40 };
    float* sVl[2] = { sm + 2 * 128 * 36 + 2 * 64 * 40, sm + 2 * 128 * 36 + 3 * 64 * 40 };
    uint32_t sAa[2]  = { smem_u32(sA[0]),  smem_u32(sA[1]) };
    uint32_t sVha[2] = { smem_u32(sVh[0]), smem_u32(sVh[1]) };
    uint32_t sVla[2] = { smem_u32(sVl[0]), smem_u32(sVl[1]) };

    const int tid = threadIdx.x;
    const int bh = blockIdx.y, q0 = blockIdx.x * 128;
    const int w = tid >> 5, lane = tid & 31;
    const int g = lane >> 2, t4 = lane & 3;
    const int lrA = tid >> 1, lcA = (tid & 1) * 16;   // A: 128 rows x 32
    const int lrV = tid >> 2, lcV = (tid & 3) * 8;    // V^T: 64 d-rows x 32

    const float* arow  = A + ((size_t)(bh * N_SEQ + q0 + lrA)) * N_SEQ + lcA;
    const float* vhrow = g_Vth + ((size_t)bh * 64 + lrV) * N_SEQ + lcV;
    const float* vlrow = g_Vtl + ((size_t)bh * 64 + lrV) * N_SEQ + lcV;

    auto prefetch = [&](int kt, int buf) {
        const int off = kt * 32;
#pragma unroll
        for (int i = 0; i < 4; i++)
            cp16(sAa[buf] + (lrA * 36 + lcA + i * 4) * 4, arow + off + i * 4);
#pragma unroll
        for (int i = 0; i < 2; i++) {
            cp16(sVha[buf] + (lrV * 40 + lcV + i * 4) * 4, vhrow + off + i * 4);
            cp16(sVla[buf] + (lrV * 40 + lcV + i * 4) * 4, vlrow + off + i * 4);
        }
        CP_COMMIT();
    };

    float acc[8][4];
#pragma unroll
    for (int i = 0; i < 8; i++)
#pragma unroll
        for (int j = 0; j < 4; j++) acc[i][j] = 0.f;

    prefetch(0, 0);
    for (int kt = 0; kt < 64; kt++) {
        const int buf = kt & 1;
        if (kt < 63) { prefetch(kt + 1, buf ^ 1); CP_WAIT(1); }
        else         { CP_WAIT(0); }
        __syncthreads();

#pragma unroll
        for (int kf = 0; kf < 4; kf++) {
            uint32_t ah[4], al[4];
            lda_hl(ah, al, sA[buf] + (w * 16 + g) * 36 + kf * 8 + t4, 36);
#pragma unroll
            for (int nf = 0; nf < 8; nf++) {
                const int bo = (nf * 8 + g) * 40 + kf * 8 + t4 * 2;
                float2 h2 = *(const float2*)&sVh[buf][bo];
                float2 l2 = *(const float2*)&sVl[buf][bo];
                uint32_t bh2[2] = { __float_as_uint(h2.x), __float_as_uint(h2.y) };
                uint32_t bl2[2] = { __float_as_uint(l2.x), __float_as_uint(l2.y) };
                mma3(acc[nf], ah, al, bh2, bl2);
            }
        }
        __syncthreads();
    }

    const int b = bh >> 3, h = bh & 7;
    float* dst0 = g_P + ((size_t)(b * N_SEQ + q0 + w * 16 + g)) * C_DIM + h * 64;
    float* dst1 = dst0 + 8 * C_DIM;
#pragma unroll
    for (int nf = 0; nf < 8; nf++) {
        const int c = nf * 8 + t4 * 2;
        *(float2*)(dst0 + c) = make_float2(acc[nf][0], acc[nf][1]);
        *(float2*)(dst1 + c) = make_float2(acc[nf][2], acc[nf][3]);
    }
}

// ---------------------------------------------------------------------------
extern "C" void kernel_launch(void* const* d_in, const int* in_sizes, int n_in,
                              void* d_out, int out_size)
{
    const float* x  = (const float*)d_in[0];
    const float* Wq = (const float*)d_in[1];
    const float* bq = (const float*)d_in[2];
    const float* Wk = (const float*)d_in[3];
    const float* bk = (const float*)d_in[4];
    const float* Wv = (const float*)d_in[5];
    const float* bv = (const float*)d_in[6];
    const float* Wo = (const float*)d_in[7];
    const float* bo = (const float*)d_in[8];

    float *dP, *dS;
    cudaGetSymbolAddress((void**)&dP, g_P);
    cudaGetSymbolAddress((void**)&dS, g_S);

    float* out = (float*)d_out;
    const long long OUT_N = 2LL * N_SEQ * C_DIM;
    const long long ATT_N = (long long)N_BH * N_SEQ * N_SEQ;
    float* final_ptr = nullptr;
    float* attn_ptr  = nullptr;
    if ((long long)out_size >= OUT_N + ATT_N) { final_ptr = out; attn_ptr = out + OUT_N; }
    else if ((long long)out_size >= ATT_N)    { attn_ptr = out; }
    else                                      { final_ptr = out; }
    float* S = attn_ptr ? attn_ptr : dS;

    cudaFuncSetAttribute(proj_kernel,   cudaFuncAttributeMaxDynamicSharedMemorySize, PJ_SMEM);
    cudaFuncSetAttribute(scores_kernel, cudaFuncAttributeMaxDynamicSharedMemorySize, SC_SMEM);
    cudaFuncSetAttribute(attnv_kernel,  cudaFuncAttributeMaxDynamicSharedMemorySize, AV_SMEM);

    // pre-split weights into hi/lo (c-permuted); mats: 0=Wq 1=Wk 2=Wv 3=Wo
    wconv_kernel<<<dim3(C_DIM, 4), 128>>>(Wq, Wk, Wv, Wo);

    // Q/K/V projections in one launch (z selects weight + epilogue format)
    proj_kernel<<<dim3(32, 8, 3), 256, PJ_SMEM>>>(x, bq, bk, bv, bo, nullptr, 0);

    scores_kernel<<<dim3(16, 16), 256, SC_SMEM>>>(S);
    sparsemax_kernel<<<(N_BH * N_SEQ) / 8, 256>>>(S);
    attnv_kernel<<<dim3(16, 16), 256, AV_SMEM>>>(S);

    if (final_ptr)
        proj_kernel<<<dim3(32, 8, 1), 256, PJ_SMEM>>>(dP, bq, bk, bv, bo, final_ptr, 3);
}

// round 9
// speedup vs baseline: 2.3823x; 1.0708x over previous
#include <cuda_runtime.h>
#include <cstdint>

#define N_SEQ 2048
#define C_DIM 512
#define N_BH  16

// ---- device-global scratch (no allocation allowed) ----
__device__ float g_Qi [N_BH * N_SEQ * 128];   // Q hi/lo interleaved, 1/8 folded
__device__ float g_Ki [N_BH * N_SEQ * 128];   // K hi/lo interleaved
__device__ float g_Vti[N_BH * 64 * 2 * N_SEQ];// V^T hi/lo interleaved [bh][d][4096]
__device__ float g_P  [2 * N_SEQ * C_DIM];
__device__ float g_S  [(size_t)N_BH * N_SEQ * N_SEQ];
__device__ float g_Wi [4 * C_DIM * 2 * C_DIM];// W hi/lo interleaved [mat][n][1024]

// ============================ helpers ============================
__device__ __forceinline__ uint32_t f2tf(float x) {
    uint32_t r; asm("cvt.rna.tf32.f32 %0, %1;" : "=r"(r) : "f"(x)); return r;
}
__device__ __forceinline__ uint32_t smem_u32(const void* p) {
    uint32_t a;
    asm("{ .reg .u64 t; cvta.to.shared.u64 t, %1; cvt.u32.u64 %0, t; }" : "=r"(a) : "l"(p));
    return a;
}
__device__ __forceinline__ void cp16(uint32_t s, const void* g) {
    asm volatile("cp.async.cg.shared.global [%0], [%1], 16;" :: "r"(s), "l"(g) : "memory");
}
#define CP_COMMIT() asm volatile("cp.async.commit_group;" ::: "memory")
#define CP_WAIT(n)  asm volatile("cp.async.wait_group %0;" :: "n"(n) : "memory")

__device__ __forceinline__ void mma8(float* d, const uint32_t* a, const uint32_t* b) {
    asm volatile(
        "mma.sync.aligned.m16n8k8.row.col.f32.tf32.tf32.f32 "
        "{%0,%1,%2,%3}, {%4,%5,%6,%7}, {%8,%9}, {%0,%1,%2,%3};"
        : "+f"(d[0]), "+f"(d[1]), "+f"(d[2]), "+f"(d[3])
        : "r"(a[0]), "r"(a[1]), "r"(a[2]), "r"(a[3]), "r"(b[0]), "r"(b[1]));
}
__device__ __forceinline__ void cvt_hl(float x, uint32_t& h, uint32_t& l) {
    h = f2tf(x);
    l = f2tf(x - __uint_as_float(h));
}
// raw A fragment from smem + in-register hi/lo split (attn / X operands)
__device__ __forceinline__ void lda_hl(uint32_t* h, uint32_t* l, const float* p, int st) {
    cvt_hl(p[0], h[0], l[0]);
    cvt_hl(p[8 * st], h[1], l[1]);
    cvt_hl(p[4], h[2], l[2]);
    cvt_hl(p[8 * st + 4], h[3], l[3]);
}
__device__ __forceinline__ void mma3(float* acc, const uint32_t* ah, const uint32_t* al,
                                     const uint32_t* bh, const uint32_t* bl) {
    mma8(acc, ah, bh);
    mma8(acc, al, bh);
    mma8(acc, ah, bl);
}
// interleaved hi/lo position: 8-group of c -> 16 floats {h(p),h(p+4),l(p),l(p+4)}x4
__device__ __forceinline__ int ilv(int c) {
    return ((c & ~7) << 1) + ((c & 3) << 2) + ((c >> 2) & 1);
}
__device__ __forceinline__ float u2f(uint32_t x) { return __uint_as_float(x); }

// =================== weight pre-split (hi/lo interleaved) ===================
__global__ void wconv_kernel(const float* __restrict__ W0, const float* __restrict__ W1,
                             const float* __restrict__ W2, const float* __restrict__ W3)
{
    const int mat = blockIdx.y;
    const float* W = (mat == 0) ? W0 : (mat == 1) ? W1 : (mat == 2) ? W2 : W3;
    const int n = blockIdx.x;
    float* dst = g_Wi + ((size_t)mat * C_DIM + n) * 1024;
    for (int c = threadIdx.x; c < C_DIM; c += blockDim.x) {
        uint32_t h, l; cvt_hl(W[n * C_DIM + c], h, l);
        const int p = ilv(c);
        dst[p] = u2f(h); dst[p + 2] = u2f(l);
    }
}

// ======================= projection GEMM (3xTF32) =======================
// Y = X @ W^T + bias.  CTA: 128m x 64n, BK=32 double-buffered; 8 warps = 16m.
// z: 0=Q interleaved (1/8 folded), 1=K interleaved, 2=V^T interleaved, 3=flat.
#define PJ_SMEM ((2 * 128 * 36 + 2 * 64 * 80) * 4)   // 77,824 B -> 2 CTAs/SM

__global__ __launch_bounds__(256, 2)
void proj_kernel(const float* __restrict__ X,
                 const float* __restrict__ b0, const float* __restrict__ b1,
                 const float* __restrict__ b2, const float* __restrict__ b3,
                 float* __restrict__ out_final, int zbase)
{
    extern __shared__ float sm[];
    float* sX[2] = { sm, sm + 128 * 36 };
    float* sW[2] = { sm + 2 * 128 * 36, sm + 2 * 128 * 36 + 64 * 80 };
    uint32_t sXa[2] = { smem_u32(sX[0]), smem_u32(sX[1]) };
    uint32_t sWa[2] = { smem_u32(sW[0]), smem_u32(sW[1]) };

    const int z = zbase + blockIdx.z;
    const float* bias = (z == 0) ? b0 : (z == 1) ? b1 : (z == 2) ? b2 : b3;
    const float* Wi = g_Wi + (size_t)z * C_DIM * 1024;

    const int tid = threadIdx.x;
    const int m0 = blockIdx.x * 128, n0 = blockIdx.y * 64;
    const int w = tid >> 5, lane = tid & 31;
    const int g = lane >> 2, t4 = lane & 3;
    const int lrX = tid >> 1, lcX = (tid & 1) * 16;   // X: 128 rows x 32 raw
    const int lrW = tid >> 2, lcW = (tid & 3) * 16;   // Wi: 64 rows x 64 ilv

    const float* xrow = X + (size_t)(m0 + lrX) * C_DIM + lcX;
    const float* wrow = Wi + (size_t)(n0 + lrW) * 1024 + lcW;

    auto prefetch = [&](int t, int buf) {
#pragma unroll
        for (int i = 0; i < 4; i++)
            cp16(sXa[buf] + (lrX * 36 + lcX + i * 4) * 4, xrow + t * 32 + i * 4);
#pragma unroll
        for (int i = 0; i < 4; i++)
            cp16(sWa[buf] + (lrW * 80 + lcW + i * 4) * 4, wrow + t * 64 + i * 4);
        CP_COMMIT();
    };

    float acc[8][4];
#pragma unroll
    for (int i = 0; i < 8; i++)
#pragma unroll
        for (int j = 0; j < 4; j++) acc[i][j] = 0.f;

    prefetch(0, 0);
    for (int t = 0; t < 16; t++) {
        const int buf = t & 1;
        if (t < 15) { prefetch(t + 1, buf ^ 1); CP_WAIT(1); }
        else        { CP_WAIT(0); }
        __syncthreads();
#pragma unroll
        for (int kf = 0; kf < 4; kf++) {
            uint32_t ah[4], al[4];
            lda_hl(ah, al, sX[buf] + (w * 16 + g) * 36 + kf * 8 + t4, 36);
#pragma unroll
            for (int nf = 0; nf < 8; nf++) {
                float4 b4 = *(const float4*)&sW[buf][(nf * 8 + g) * 80 + kf * 16 + t4 * 4];
                uint32_t bh2[2] = { __float_as_uint(b4.x), __float_as_uint(b4.y) };
                uint32_t bl2[2] = { __float_as_uint(b4.z), __float_as_uint(b4.w) };
                mma3(acc[nf], ah, al, bh2, bl2);
            }
        }
        __syncthreads();
    }

    const int m = m0 + w * 16 + g;
#pragma unroll
    for (int nf = 0; nf < 8; nf++) {
        const int j = n0 + nf * 8 + t4 * 2;
        const float bx = bias[j], by = bias[j + 1];
        float v0 = acc[nf][0] + bx, v1 = acc[nf][1] + by;   // row m
        float v2 = acc[nf][2] + bx, v3 = acc[nf][3] + by;   // row m+8
        if (z == 3) {
            *(float2*)(out_final + (size_t)m * C_DIM + j)       = make_float2(v0, v1);
            *(float2*)(out_final + (size_t)(m + 8) * C_DIM + j) = make_float2(v2, v3);
        } else {
            const int b = m >> 11, n = m & 2047;
            const int h = j >> 6, d0 = j & 63;
            const int bh = b * 8 + h;
            uint32_t hh, ll;
            if (z == 0) {          // Q interleaved, scale 1/8 folded (exact)
                const size_t r0 = ((size_t)bh * N_SEQ + n) * 128;
                const size_t r1 = r0 + 8 * 128;
                const int i0 = ilv(d0), i1 = ilv(d0 + 1);
                cvt_hl(v0 * 0.125f, hh, ll); g_Qi[r0 + i0] = u2f(hh); g_Qi[r0 + i0 + 2] = u2f(ll);
                cvt_hl(v1 * 0.125f, hh, ll); g_Qi[r0 + i1] = u2f(hh); g_Qi[r0 + i1 + 2] = u2f(ll);
                cvt_hl(v2 * 0.125f, hh, ll); g_Qi[r1 + i0] = u2f(hh); g_Qi[r1 + i0 + 2] = u2f(ll);
                cvt_hl(v3 * 0.125f, hh, ll); g_Qi[r1 + i1] = u2f(hh); g_Qi[r1 + i1 + 2] = u2f(ll);
            } else if (z == 1) {   // K interleaved
                const size_t r0 = ((size_t)bh * N_SEQ + n) * 128;
                const size_t r1 = r0 + 8 * 128;
                const int i0 = ilv(d0), i1 = ilv(d0 + 1);
                cvt_hl(v0, hh, ll); g_Ki[r0 + i0] = u2f(hh); g_Ki[r0 + i0 + 2] = u2f(ll);
                cvt_hl(v1, hh, ll); g_Ki[r0 + i1] = u2f(hh); g_Ki[r0 + i1 + 2] = u2f(ll);
                cvt_hl(v2, hh, ll); g_Ki[r1 + i0] = u2f(hh); g_Ki[r1 + i0 + 2] = u2f(ll);
                cvt_hl(v3, hh, ll); g_Ki[r1 + i1] = u2f(hh); g_Ki[r1 + i1 + 2] = u2f(ll);
            } else {               // V^T interleaved: rows d0,d0+1; tokens n,n+8
                const size_t r0 = ((size_t)bh * 64 + d0) * 4096;
                const size_t r1 = r0 + 4096;
                const int in0 = ilv(n), in8 = ilv(n + 8);
                cvt_hl(v0, hh, ll); g_Vti[r0 + in0] = u2f(hh); g_Vti[r0 + in0 + 2] = u2f(ll);
                cvt_hl(v1, hh, ll); g_Vti[r1 + in0] = u2f(hh); g_Vti[r1 + in0 + 2] = u2f(ll);
                cvt_hl(v2, hh, ll); g_Vti[r0 + in8] = u2f(hh); g_Vti[r0 + in8 + 2] = u2f(ll);
                cvt_hl(v3, hh, ll); g_Vti[r1 + in8] = u2f(hh); g_Vti[r1 + in8 + 2] = u2f(ll);
            }
        }
    }
}

// ======================= scores kernel (3xTF32) =======================
// S[q,:] = scaled Q K^T (scale folded into Q).  CTA: (bh, 128 q), 32 token-tiles.
// Both operands pre-split interleaved: A = 2x LDS.128, B = 1x LDS.128, zero cvt.
#define SC_SMEM ((128 * 144 + 64 * 144) * 4)   // 110,592 B -> 2 CTAs/SM

__global__ __launch_bounds__(256, 2)
void scores_kernel(float* __restrict__ S)
{
    extern __shared__ float sm[];
    float* sQ = sm;               // 128 rows x 144 (128 ilv floats + pad)
    float* sK = sm + 128 * 144;   // 64 rows x 144
    const uint32_t sQa = smem_u32(sQ), sKa = smem_u32(sK);

    const int tid = threadIdx.x;
    const int bh = blockIdx.y, q0 = blockIdx.x * 128;
    const int w = tid >> 5, lane = tid & 31;
    const int g = lane >> 2, t4 = lane & 3;

    {   // Q tile: 128 rows x 128 floats
        const int lr = tid >> 1, lc = (tid & 1) * 64;
        const float* qs = g_Qi + ((size_t)bh * N_SEQ + q0 + lr) * 128 + lc;
#pragma unroll
        for (int i = 0; i < 16; i++)
            cp16(sQa + (lr * 144 + lc + i * 4) * 4, qs + i * 4);
        CP_COMMIT();
    }
    const int lrK = tid >> 2, lcK = (tid & 3) * 32;
    const float* krow = g_Ki + ((size_t)bh * N_SEQ + lrK) * 128 + lcK;
    auto prefetchK = [&](int kt) {
        const size_t off = (size_t)kt * 64 * 128;
#pragma unroll
        for (int i = 0; i < 8; i++)
            cp16(sKa + (lrK * 144 + lcK + i * 4) * 4, krow + off + i * 4);
        CP_COMMIT();
    };

    prefetchK(0);
    for (int kt = 0; kt < 32; kt++) {
        CP_WAIT(0);
        __syncthreads();

        float acc[8][4];
#pragma unroll
        for (int i = 0; i < 8; i++)
#pragma unroll
            for (int j = 0; j < 4; j++) acc[i][j] = 0.f;

#pragma unroll
        for (int kf = 0; kf < 8; kf++) {
            float4 qa = *(const float4*)&sQ[(w * 16 + g) * 144 + kf * 16 + t4 * 4];
            float4 qb = *(const float4*)&sQ[(w * 16 + g + 8) * 144 + kf * 16 + t4 * 4];
            uint32_t ah[4] = { __float_as_uint(qa.x), __float_as_uint(qb.x),
                               __float_as_uint(qa.y), __float_as_uint(qb.y) };
            uint32_t al[4] = { __float_as_uint(qa.z), __float_as_uint(qb.z),
                               __float_as_uint(qa.w), __float_as_uint(qb.w) };
#pragma unroll
            for (int nf = 0; nf < 8; nf++) {
                float4 kb = *(const float4*)&sK[(nf * 8 + g) * 144 + kf * 16 + t4 * 4];
                uint32_t bh2[2] = { __float_as_uint(kb.x), __float_as_uint(kb.y) };
                uint32_t bl2[2] = { __float_as_uint(kb.z), __float_as_uint(kb.w) };
                mma3(acc[nf], ah, al, bh2, bl2);
            }
        }
        __syncthreads();
        if (kt < 31) prefetchK(kt + 1);   // overlaps with S store below

        float* dst0 = S + ((size_t)(bh * N_SEQ + q0 + w * 16 + g)) * N_SEQ + kt * 64;
        float* dst1 = dst0 + 8 * N_SEQ;
#pragma unroll
        for (int nf = 0; nf < 8; nf++) {
            const int c = nf * 8 + t4 * 2;
            *(float2*)(dst0 + c) = make_float2(acc[nf][0], acc[nf][1]);
            *(float2*)(dst1 + c) = make_float2(acc[nf][2], acc[nf][3]);
        }
    }
}

// ======================= sparsemax kernel (v2) =======================
// Row per warp, streamed through L1 (no big register file): pass1 max,
// pass2 filter (> max-1) via single predicated STS into per-warp shared slots,
// Newton over <=8 register candidates, pass3 writeback. Exact fallback scans
// global (L1-hot) if any lane has >8 candidates.
__global__ __launch_bounds__(256)
void sparsemax_kernel(float* __restrict__ A)
{
    __shared__ float cand[8 * 8 * 32];   // [warp][slot][lane]
    const int lane = threadIdx.x & 31;
    const int warp = threadIdx.x >> 5;
    const size_t row = (size_t)blockIdx.x * 8 + warp;
    const float4* r4 = (const float4*)(A + row * N_SEQ);
    float4* w4 = (float4*)(A + row * N_SEQ);

    float m = -3.402823466e38f;
#pragma unroll 4
    for (int i = 0; i < 16; i++) {
        float4 v = r4[i * 32 + lane];
        m = fmaxf(m, fmaxf(fmaxf(v.x, v.y), fmaxf(v.z, v.w)));
    }
#pragma unroll
    for (int o = 16; o; o >>= 1) m = fmaxf(m, __shfl_xor_sync(0xffffffffu, m, o));
    const float thr = m - 1.0f;

    // filter: candidates > thr into shared slots (single predicated STS each)
    float* cw = cand + warp * 256 + lane;
    int cnt = 0;
#pragma unroll 4
    for (int i = 0; i < 16; i++) {
        float4 v = r4[i * 32 + lane];   // L1 hit
        float e[4] = { v.x, v.y, v.z, v.w };
#pragma unroll
        for (int c = 0; c < 4; c++) {
            if (e[c] > thr) {
                if (cnt < 8) cw[cnt * 32] = e[c];
                cnt++;
            }
        }
    }
    __syncwarp();

    float tau = thr;
    if (__ballot_sync(0xffffffffu, cnt > 8)) {
        // exact fallback: full-scan Newton over global row (rare, L1-hot)
        for (int it = 0; it < 64; ++it) {
            float Ss = 0.f; int k = 0;
#pragma unroll 4
            for (int i = 0; i < 16; i++) {
                float4 v = r4[i * 32 + lane];
                float d;
                d = v.x - tau; if (d > 0.f) { Ss += d; k++; }
                d = v.y - tau; if (d > 0.f) { Ss += d; k++; }
                d = v.z - tau; if (d > 0.f) { Ss += d; k++; }
                d = v.w - tau; if (d > 0.f) { Ss += d; k++; }
            }
#pragma unroll
            for (int o = 16; o; o >>= 1) {
                Ss += __shfl_xor_sync(0xffffffffu, Ss, o);
                k  += __shfl_xor_sync(0xffffffffu, k, o);
            }
            if (k == 0) break;
            const float delta = (Ss - 1.0f) / (float)k;
            tau += delta;
            if (fabsf(delta) < 1e-8f) break;
        }
    } else {
        float cb[8];
#pragma unroll
        for (int j = 0; j < 8; j++) cb[j] = cw[j * 32];   // masked by cnt below
        for (int it = 0; it < 64; ++it) {
            float Ss = 0.f; int k = 0;
#pragma unroll
            for (int j = 0; j < 8; j++) {
                float d = cb[j] - tau;
                if (j < cnt && d > 0.f) { Ss += d; k++; }
            }
#pragma unroll
            for (int o = 16; o; o >>= 1) {
                Ss += __shfl_xor_sync(0xffffffffu, Ss, o);
                k  += __shfl_xor_sync(0xffffffffu, k, o);
            }
            if (k == 0) break;
            const float delta = (Ss - 1.0f) / (float)k;
            tau += delta;
            if (fabsf(delta) < 1e-8f) break;
        }
    }

#pragma unroll 4
    for (int i = 0; i < 16; i++) {
        float4 v = r4[i * 32 + lane];
        float4 o;
        o.x = fmaxf(v.x - tau, 0.f); o.y = fmaxf(v.y - tau, 0.f);
        o.z = fmaxf(v.z - tau, 0.f); o.w = fmaxf(v.w - tau, 0.f);
        w4[i * 32 + lane] = o;
    }
}

// ======================= attn@V kernel (3xTF32) =======================
// P[q,d] = sum_k attn[q,k] V[k,d].  CTA: (bh, 128 q), 64 token-tiles of 32,
// double-buffered. B = V^T interleaved (1x LDS.128), A raw in-reg cvt.
#define AV_SMEM ((2 * 128 * 36 + 2 * 64 * 80) * 4)   // 77,824 B -> 2 CTAs/SM

__global__ __launch_bounds__(256, 2)
void attnv_kernel(const float* __restrict__ A)
{
    extern __shared__ float sm[];
    float* sA[2] = { sm, sm + 128 * 36 };
    float* sV[2] = { sm + 2 * 128 * 36, sm + 2 * 128 * 36 + 64 * 80 };
    uint32_t sAa[2] = { smem_u32(sA[0]), smem_u32(sA[1]) };
    uint32_t sVa[2] = { smem_u32(sV[0]), smem_u32(sV[1]) };

    const int tid = threadIdx.x;
    const int bh = blockIdx.y, q0 = blockIdx.x * 128;
    const int w = tid >> 5, lane = tid & 31;
    const int g = lane >> 2, t4 = lane & 3;
    const int lrA = tid >> 1, lcA = (tid & 1) * 16;   // A: 128 rows x 32 raw
    const int lrV = tid >> 2, lcV = (tid & 3) * 16;   // V^T: 64 d-rows x 64 ilv

    const float* arow = A + ((size_t)(bh * N_SEQ + q0 + lrA)) * N_SEQ + lcA;
    const float* vrow = g_Vti + ((size_t)bh * 64 + lrV) * 4096 + lcV;

    auto prefetch = [&](int kt, int buf) {
#pragma unroll
        for (int i = 0; i < 4; i++)
            cp16(sAa[buf] + (lrA * 36 + lcA + i * 4) * 4, arow + kt * 32 + i * 4);
#pragma unroll
        for (int i = 0; i < 4; i++)
            cp16(sVa[buf] + (lrV * 80 + lcV + i * 4) * 4, vrow + kt * 64 + i * 4);
        CP_COMMIT();
    };

    float acc[8][4];
#pragma unroll
    for (int i = 0; i < 8; i++)
#pragma unroll
        for (int j = 0; j < 4; j++) acc[i][j] = 0.f;

    prefetch(0, 0);
    for (int kt = 0; kt < 64; kt++) {
        const int buf = kt & 1;
        if (kt < 63) { prefetch(kt + 1, buf ^ 1); CP_WAIT(1); }
        else         { CP_WAIT(0); }
        __syncthreads();

#pragma unroll
        for (int kf = 0; kf < 4; kf++) {
            uint32_t ah[4], al[4];
            lda_hl(ah, al, sA[buf] + (w * 16 + g) * 36 + kf * 8 + t4, 36);
#pragma unroll
            for (int nf = 0; nf < 8; nf++) {
                float4 vb = *(const float4*)&sV[buf][(nf * 8 + g) * 80 + kf * 16 + t4 * 4];
                uint32_t bh2[2] = { __float_as_uint(vb.x), __float_as_uint(vb.y) };
                uint32_t bl2[2] = { __float_as_uint(vb.z), __float_as_uint(vb.w) };
                mma3(acc[nf], ah, al, bh2, bl2);
            }
        }
        __syncthreads();
    }

    const int b = bh >> 3, h = bh & 7;
    float* dst0 = g_P + ((size_t)(b * N_SEQ + q0 + w * 16 + g)) * C_DIM + h * 64;
    float* dst1 = dst0 + 8 * C_DIM;
#pragma unroll
    for (int nf = 0; nf < 8; nf++) {
        const int c = nf * 8 + t4 * 2;
        *(float2*)(dst0 + c) = make_float2(acc[nf][0], acc[nf][1]);
        *(float2*)(dst1 + c) = make_float2(acc[nf][2], acc[nf][3]);
    }
}

// ---------------------------------------------------------------------------
extern "C" void kernel_launch(void* const* d_in, const int* in_sizes, int n_in,
                              void* d_out, int out_size)
{
    const float* x  = (const float*)d_in[0];
    const float* Wq = (const float*)d_in[1];
    const float* bq = (const float*)d_in[2];
    const float* Wk = (const float*)d_in[3];
    const float* bk = (const float*)d_in[4];
    const float* Wv = (const float*)d_in[5];
    const float* bv = (const float*)d_in[6];
    const float* Wo = (const float*)d_in[7];
    const float* bo = (const float*)d_in[8];

    float *dP, *dS;
    cudaGetSymbolAddress((void**)&dP, g_P);
    cudaGetSymbolAddress((void**)&dS, g_S);

    float* out = (float*)d_out;
    const long long OUT_N = 2LL * N_SEQ * C_DIM;
    const long long ATT_N = (long long)N_BH * N_SEQ * N_SEQ;
    float* final_ptr = nullptr;
    float* attn_ptr  = nullptr;
    if ((long long)out_size >= OUT_N + ATT_N) { final_ptr = out; attn_ptr = out + OUT_N; }
    else if ((long long)out_size >= ATT_N)    { attn_ptr = out; }
    else                                      { final_ptr = out; }
    float* S = attn_ptr ? attn_ptr : dS;

    cudaFuncSetAttribute(proj_kernel,   cudaFuncAttributeMaxDynamicSharedMemorySize, PJ_SMEM);
    cudaFuncSetAttribute(scores_kernel, cudaFuncAttributeMaxDynamicSharedMemorySize, SC_SMEM);
    cudaFuncSetAttribute(attnv_kernel,  cudaFuncAttributeMaxDynamicSharedMemorySize, AV_SMEM);

    // pre-split weights into hi/lo interleaved; mats: 0=Wq 1=Wk 2=Wv 3=Wo
    wconv_kernel<<<dim3(C_DIM, 4), 128>>>(Wq, Wk, Wv, Wo);

    // Q/K/V projections in one launch (z selects weight + epilogue format)
    proj_kernel<<<dim3(32, 8, 3), 256, PJ_SMEM>>>(x, bq, bk, bv, bo, nullptr, 0);

    scores_kernel<<<dim3(16, 16), 256, SC_SMEM>>>(S);
    sparsemax_kernel<<<(N_BH * N_SEQ) / 8, 256>>>(S);
    attnv_kernel<<<dim3(16, 16), 256, AV_SMEM>>>(S);

    if (final_ptr)
        proj_kernel<<<dim3(32, 8, 1), 256, PJ_SMEM>>>(dP, bq, bk, bv, bo, final_ptr, 3);
}

// round 10
// speedup vs baseline: 2.4104x; 1.0118x over previous
#include <cuda_runtime.h>
#include <cstdint>

#define N_SEQ 2048
#define C_DIM 512
#define N_BH  16

// ---- device-global scratch (no allocation allowed) ----
__device__ float g_Qi [N_BH * N_SEQ * 128];   // Q hi/lo interleaved, 1/8 folded
__device__ float g_Ki [N_BH * N_SEQ * 128];   // K hi/lo interleaved
__device__ float g_Vti[N_BH * 64 * 2 * N_SEQ];// V^T hi/lo interleaved [bh][d][4096]
__device__ float g_P  [2 * N_SEQ * C_DIM];
__device__ float g_S  [(size_t)N_BH * N_SEQ * N_SEQ];
__device__ float g_Wi [4 * C_DIM * 2 * C_DIM];// W hi/lo interleaved [mat][n][1024]
__device__ float g_rowmax[N_BH * N_SEQ];      // per-row score max (from scores)

// ============================ helpers ============================
__device__ __forceinline__ uint32_t f2tf(float x) {
    uint32_t r; asm("cvt.rna.tf32.f32 %0, %1;" : "=r"(r) : "f"(x)); return r;
}
__device__ __forceinline__ uint32_t smem_u32(const void* p) {
    uint32_t a;
    asm("{ .reg .u64 t; cvta.to.shared.u64 t, %1; cvt.u32.u64 %0, t; }" : "=r"(a) : "l"(p));
    return a;
}
__device__ __forceinline__ void cp16(uint32_t s, const void* g) {
    asm volatile("cp.async.cg.shared.global [%0], [%1], 16;" :: "r"(s), "l"(g) : "memory");
}
#define CP_COMMIT() asm volatile("cp.async.commit_group;" ::: "memory")
#define CP_WAIT(n)  asm volatile("cp.async.wait_group %0;" :: "n"(n) : "memory")

__device__ __forceinline__ void mma8(float* d, const uint32_t* a, const uint32_t* b) {
    asm volatile(
        "mma.sync.aligned.m16n8k8.row.col.f32.tf32.tf32.f32 "
        "{%0,%1,%2,%3}, {%4,%5,%6,%7}, {%8,%9}, {%0,%1,%2,%3};"
        : "+f"(d[0]), "+f"(d[1]), "+f"(d[2]), "+f"(d[3])
        : "r"(a[0]), "r"(a[1]), "r"(a[2]), "r"(a[3]), "r"(b[0]), "r"(b[1]));
}
__device__ __forceinline__ void cvt_hl(float x, uint32_t& h, uint32_t& l) {
    h = f2tf(x);
    l = f2tf(x - __uint_as_float(h));
}
// raw A fragment from smem + in-register hi/lo split (attn / X operands)
__device__ __forceinline__ void lda_hl(uint32_t* h, uint32_t* l, const float* p, int st) {
    cvt_hl(p[0], h[0], l[0]);
    cvt_hl(p[8 * st], h[1], l[1]);
    cvt_hl(p[4], h[2], l[2]);
    cvt_hl(p[8 * st + 4], h[3], l[3]);
}
__device__ __forceinline__ void mma3(float* acc, const uint32_t* ah, const uint32_t* al,
                                     const uint32_t* bh, const uint32_t* bl) {
    mma8(acc, ah, bh);
    mma8(acc, al, bh);
    mma8(acc, ah, bl);
}
// interleaved hi/lo position: 8-group of c -> 16 floats {h(p),h(p+4),l(p),l(p+4)}x4
__device__ __forceinline__ int ilv(int c) {
    return ((c & ~7) << 1) + ((c & 3) << 2) + ((c >> 2) & 1);
}
__device__ __forceinline__ float u2f(uint32_t x) { return __uint_as_float(x); }

// =================== weight pre-split (hi/lo interleaved) ===================
__global__ void wconv_kernel(const float* __restrict__ W0, const float* __restrict__ W1,
                             const float* __restrict__ W2, const float* __restrict__ W3)
{
    const int mat = blockIdx.y;
    const float* W = (mat == 0) ? W0 : (mat == 1) ? W1 : (mat == 2) ? W2 : W3;
    const int n = blockIdx.x;
    float* dst = g_Wi + ((size_t)mat * C_DIM + n) * 1024;
    for (int c = threadIdx.x; c < C_DIM; c += blockDim.x) {
        uint32_t h, l; cvt_hl(W[n * C_DIM + c], h, l);
        const int p = ilv(c);
        dst[p] = u2f(h); dst[p + 2] = u2f(l);
    }
}

// ======================= projection GEMM (3xTF32) =======================
// Y = X @ W^T + bias.  CTA: 128m x 64n, BK=32 double-buffered; 8 warps = 16m.
// z: 0=Q interleaved (1/8 folded), 1=K interleaved, 2=V^T interleaved, 3=flat.
#define PJ_SMEM ((2 * 128 * 36 + 2 * 64 * 80) * 4)   // 77,824 B -> 2 CTAs/SM

__global__ __launch_bounds__(256, 2)
void proj_kernel(const float* __restrict__ X,
                 const float* __restrict__ b0, const float* __restrict__ b1,
                 const float* __restrict__ b2, const float* __restrict__ b3,
                 float* __restrict__ out_final, int zbase)
{
    extern __shared__ float sm[];
    float* sX[2] = { sm, sm + 128 * 36 };
    float* sW[2] = { sm + 2 * 128 * 36, sm + 2 * 128 * 36 + 64 * 80 };
    uint32_t sXa[2] = { smem_u32(sX[0]), smem_u32(sX[1]) };
    uint32_t sWa[2] = { smem_u32(sW[0]), smem_u32(sW[1]) };

    const int z = zbase + blockIdx.z;
    const float* bias = (z == 0) ? b0 : (z == 1) ? b1 : (z == 2) ? b2 : b3;
    const float* Wi = g_Wi + (size_t)z * C_DIM * 1024;

    const int tid = threadIdx.x;
    const int m0 = blockIdx.x * 128, n0 = blockIdx.y * 64;
    const int w = tid >> 5, lane = tid & 31;
    const int g = lane >> 2, t4 = lane & 3;
    const int lrX = tid >> 1, lcX = (tid & 1) * 16;   // X: 128 rows x 32 raw
    const int lrW = tid >> 2, lcW = (tid & 3) * 16;   // Wi: 64 rows x 64 ilv

    const float* xrow = X + (size_t)(m0 + lrX) * C_DIM + lcX;
    const float* wrow = Wi + (size_t)(n0 + lrW) * 1024 + lcW;

    auto prefetch = [&](int t, int buf) {
#pragma unroll
        for (int i = 0; i < 4; i++)
            cp16(sXa[buf] + (lrX * 36 + lcX + i * 4) * 4, xrow + t * 32 + i * 4);
#pragma unroll
        for (int i = 0; i < 4; i++)
            cp16(sWa[buf] + (lrW * 80 + lcW + i * 4) * 4, wrow + t * 64 + i * 4);
        CP_COMMIT();
    };

    float acc[8][4];
#pragma unroll
    for (int i = 0; i < 8; i++)
#pragma unroll
        for (int j = 0; j < 4; j++) acc[i][j] = 0.f;

    prefetch(0, 0);
    for (int t = 0; t < 16; t++) {
        const int buf = t & 1;
        if (t < 15) { prefetch(t + 1, buf ^ 1); CP_WAIT(1); }
        else        { CP_WAIT(0); }
        __syncthreads();
#pragma unroll
        for (int kf = 0; kf < 4; kf++) {
            uint32_t ah[4], al[4];
            lda_hl(ah, al, sX[buf] + (w * 16 + g) * 36 + kf * 8 + t4, 36);
#pragma unroll
            for (int nf = 0; nf < 8; nf++) {
                float4 b4 = *(const float4*)&sW[buf][(nf * 8 + g) * 80 + kf * 16 + t4 * 4];
                uint32_t bh2[2] = { __float_as_uint(b4.x), __float_as_uint(b4.y) };
                uint32_t bl2[2] = { __float_as_uint(b4.z), __float_as_uint(b4.w) };
                mma3(acc[nf], ah, al, bh2, bl2);
            }
        }
        __syncthreads();
    }

    const int m = m0 + w * 16 + g;
#pragma unroll
    for (int nf = 0; nf < 8; nf++) {
        const int j = n0 + nf * 8 + t4 * 2;
        const float bx = bias[j], by = bias[j + 1];
        float v0 = acc[nf][0] + bx, v1 = acc[nf][1] + by;   // row m
        float v2 = acc[nf][2] + bx, v3 = acc[nf][3] + by;   // row m+8
        if (z == 3) {
            *(float2*)(out_final + (size_t)m * C_DIM + j)       = make_float2(v0, v1);
            *(float2*)(out_final + (size_t)(m + 8) * C_DIM + j) = make_float2(v2, v3);
        } else {
            const int b = m >> 11, n = m & 2047;
            const int h = j >> 6, d0 = j & 63;
            const int bh = b * 8 + h;
            uint32_t hh, ll;
            if (z == 0) {          // Q interleaved, scale 1/8 folded (exact)
                const size_t r0 = ((size_t)bh * N_SEQ + n) * 128;
                const size_t r1 = r0 + 8 * 128;
                const int i0 = ilv(d0), i1 = ilv(d0 + 1);
                cvt_hl(v0 * 0.125f, hh, ll); g_Qi[r0 + i0] = u2f(hh); g_Qi[r0 + i0 + 2] = u2f(ll);
                cvt_hl(v1 * 0.125f, hh, ll); g_Qi[r0 + i1] = u2f(hh); g_Qi[r0 + i1 + 2] = u2f(ll);
                cvt_hl(v2 * 0.125f, hh, ll); g_Qi[r1 + i0] = u2f(hh); g_Qi[r1 + i0 + 2] = u2f(ll);
                cvt_hl(v3 * 0.125f, hh, ll); g_Qi[r1 + i1] = u2f(hh); g_Qi[r1 + i1 + 2] = u2f(ll);
            } else if (z == 1) {   // K interleaved
                const size_t r0 = ((size_t)bh * N_SEQ + n) * 128;
                const size_t r1 = r0 + 8 * 128;
                const int i0 = ilv(d0), i1 = ilv(d0 + 1);
                cvt_hl(v0, hh, ll); g_Ki[r0 + i0] = u2f(hh); g_Ki[r0 + i0 + 2] = u2f(ll);
                cvt_hl(v1, hh, ll); g_Ki[r0 + i1] = u2f(hh); g_Ki[r0 + i1 + 2] = u2f(ll);
                cvt_hl(v2, hh, ll); g_Ki[r1 + i0] = u2f(hh); g_Ki[r1 + i0 + 2] = u2f(ll);
                cvt_hl(v3, hh, ll); g_Ki[r1 + i1] = u2f(hh); g_Ki[r1 + i1 + 2] = u2f(ll);
            } else {               // V^T interleaved: rows d0,d0+1; tokens n,n+8
                const size_t r0 = ((size_t)bh * 64 + d0) * 4096;
                const size_t r1 = r0 + 4096;
                const int in0 = ilv(n), in8 = ilv(n + 8);
                cvt_hl(v0, hh, ll); g_Vti[r0 + in0] = u2f(hh); g_Vti[r0 + in0 + 2] = u2f(ll);
                cvt_hl(v1, hh, ll); g_Vti[r1 + in0] = u2f(hh); g_Vti[r1 + in0 + 2] = u2f(ll);
                cvt_hl(v2, hh, ll); g_Vti[r0 + in8] = u2f(hh); g_Vti[r0 + in8 + 2] = u2f(ll);
                cvt_hl(v3, hh, ll); g_Vti[r1 + in8] = u2f(hh); g_Vti[r1 + in8 + 2] = u2f(ll);
            }
        }
    }
}

// ======================= scores kernel (3xTF32) =======================
// S[q,:] = scaled Q K^T (scale folded into Q).  CTA: (bh, 128 q), 64 token-tiles
// of 32, double-buffered. Also emits per-row max into g_rowmax (fused, ~free).
#define SC_SMEM ((128 * 144 + 2 * 32 * 144) * 4)   // 110,592 B -> 2 CTAs/SM

__global__ __launch_bounds__(256, 2)
void scores_kernel(float* __restrict__ S)
{
    extern __shared__ float sm[];
    float* sQ = sm;                                    // 128 rows x 144
    float* sK[2] = { sm + 128 * 144, sm + 128 * 144 + 32 * 144 };
    const uint32_t sQa = smem_u32(sQ);
    uint32_t sKa[2] = { smem_u32(sK[0]), smem_u32(sK[1]) };

    const int tid = threadIdx.x;
    const int bh = blockIdx.y, q0 = blockIdx.x * 128;
    const int w = tid >> 5, lane = tid & 31;
    const int g = lane >> 2, t4 = lane & 3;

    {   // Q tile: 128 rows x 128 floats
        const int lr = tid >> 1, lc = (tid & 1) * 64;
        const float* qs = g_Qi + ((size_t)bh * N_SEQ + q0 + lr) * 128 + lc;
#pragma unroll
        for (int i = 0; i < 16; i++)
            cp16(sQa + (lr * 144 + lc + i * 4) * 4, qs + i * 4);
        CP_COMMIT();
    }
    const int lrK = tid >> 3, lcK = (tid & 7) * 16;   // 32 rows x 128 floats
    const float* krow = g_Ki + ((size_t)bh * N_SEQ + lrK) * 128 + lcK;
    auto prefetchK = [&](int kt, int buf) {
        const size_t off = (size_t)kt * 32 * 128;
#pragma unroll
        for (int i = 0; i < 4; i++)
            cp16(sKa[buf] + (lrK * 144 + lcK + i * 4) * 4, krow + off + i * 4);
        CP_COMMIT();
    };

    float m0 = -3.402823466e38f, m1 = -3.402823466e38f;   // row maxima

    prefetchK(0, 0);
    for (int kt = 0; kt < 64; kt++) {
        const int buf = kt & 1;
        if (kt < 63) { prefetchK(kt + 1, buf ^ 1); CP_WAIT(1); }
        else         { CP_WAIT(0); }
        __syncthreads();

        float acc[4][4];
#pragma unroll
        for (int i = 0; i < 4; i++)
#pragma unroll
            for (int j = 0; j < 4; j++) acc[i][j] = 0.f;

#pragma unroll
        for (int kf = 0; kf < 8; kf++) {
            float4 qa = *(const float4*)&sQ[(w * 16 + g) * 144 + kf * 16 + t4 * 4];
            float4 qb = *(const float4*)&sQ[(w * 16 + g + 8) * 144 + kf * 16 + t4 * 4];
            uint32_t ah[4] = { __float_as_uint(qa.x), __float_as_uint(qb.x),
                               __float_as_uint(qa.y), __float_as_uint(qb.y) };
            uint32_t al[4] = { __float_as_uint(qa.z), __float_as_uint(qb.z),
                               __float_as_uint(qa.w), __float_as_uint(qb.w) };
#pragma unroll
            for (int nf = 0; nf < 4; nf++) {
                float4 kb = *(const float4*)&sK[buf][(nf * 8 + g) * 144 + kf * 16 + t4 * 4];
                uint32_t bh2[2] = { __float_as_uint(kb.x), __float_as_uint(kb.y) };
                uint32_t bl2[2] = { __float_as_uint(kb.z), __float_as_uint(kb.w) };
                mma3(acc[nf], ah, al, bh2, bl2);
            }
        }
        __syncthreads();   // all warps done with sK[buf] before it is refilled

        float* dst0 = S + ((size_t)(bh * N_SEQ + q0 + w * 16 + g)) * N_SEQ + kt * 32;
        float* dst1 = dst0 + 8 * N_SEQ;
#pragma unroll
        for (int nf = 0; nf < 4; nf++) {
            m0 = fmaxf(m0, fmaxf(acc[nf][0], acc[nf][1]));
            m1 = fmaxf(m1, fmaxf(acc[nf][2], acc[nf][3]));
            const int c = nf * 8 + t4 * 2;
            *(float2*)(dst0 + c) = make_float2(acc[nf][0], acc[nf][1]);
            *(float2*)(dst1 + c) = make_float2(acc[nf][2], acc[nf][3]);
        }
    }

    // reduce row max over the 4 t4-lanes sharing each row, write g_rowmax
    m0 = fmaxf(m0, __shfl_xor_sync(0xffffffffu, m0, 1));
    m0 = fmaxf(m0, __shfl_xor_sync(0xffffffffu, m0, 2));
    m1 = fmaxf(m1, __shfl_xor_sync(0xffffffffu, m1, 1));
    m1 = fmaxf(m1, __shfl_xor_sync(0xffffffffu, m1, 2));
    if (t4 == 0) {
        g_rowmax[bh * N_SEQ + q0 + w * 16 + g]     = m0;
        g_rowmax[bh * N_SEQ + q0 + w * 16 + g + 8] = m1;
    }
}

// ======================= sparsemax kernel (v3) =======================
// Row per warp; max comes precomputed from scores (g_rowmax) -> only 2 passes:
// filter (candidates > max-1 into shared slots) + writeback. Newton over <=8
// register candidates; exact full-scan fallback if any lane overflows.
__global__ __launch_bounds__(256)
void sparsemax_kernel(float* __restrict__ A)
{
    __shared__ float cand[8 * 8 * 32];   // [warp][slot][lane]
    const int lane = threadIdx.x & 31;
    const int warp = threadIdx.x >> 5;
    const size_t row = (size_t)blockIdx.x * 8 + warp;
    const float4* r4 = (const float4*)(A + row * N_SEQ);
    float4* w4 = (float4*)(A + row * N_SEQ);

    const float thr = g_rowmax[row] - 1.0f;

    // filter: candidates > thr into shared slots (single predicated STS each)
    float* cw = cand + warp * 256 + lane;
    int cnt = 0;
#pragma unroll 4
    for (int i = 0; i < 16; i++) {
        float4 v = r4[i * 32 + lane];
        float e[4] = { v.x, v.y, v.z, v.w };
#pragma unroll
        for (int c = 0; c < 4; c++) {
            if (e[c] > thr) {
                if (cnt < 8) cw[cnt * 32] = e[c];
                cnt++;
            }
        }
    }
    __syncwarp();

    float tau = thr;
    if (__ballot_sync(0xffffffffu, cnt > 8)) {
        // exact fallback: full-scan Newton over global row (rare, L1-hot)
        for (int it = 0; it < 64; ++it) {
            float Ss = 0.f; int k = 0;
#pragma unroll 4
            for (int i = 0; i < 16; i++) {
                float4 v = r4[i * 32 + lane];
                float d;
                d = v.x - tau; if (d > 0.f) { Ss += d; k++; }
                d = v.y - tau; if (d > 0.f) { Ss += d; k++; }
                d = v.z - tau; if (d > 0.f) { Ss += d; k++; }
                d = v.w - tau; if (d > 0.f) { Ss += d; k++; }
            }
#pragma unroll
            for (int o = 16; o; o >>= 1) {
                Ss += __shfl_xor_sync(0xffffffffu, Ss, o);
                k  += __shfl_xor_sync(0xffffffffu, k, o);
            }
            if (k == 0) break;
            const float delta = (Ss - 1.0f) / (float)k;
            tau += delta;
            if (fabsf(delta) < 1e-8f) break;
        }
    } else {
        float cb[8];
#pragma unroll
        for (int j = 0; j < 8; j++) cb[j] = cw[j * 32];   // masked by cnt below
        for (int it = 0; it < 64; ++it) {
            float Ss = 0.f; int k = 0;
#pragma unroll
            for (int j = 0; j < 8; j++) {
                float d = cb[j] - tau;
                if (j < cnt && d > 0.f) { Ss += d; k++; }
            }
#pragma unroll
            for (int o = 16; o; o >>= 1) {
                Ss += __shfl_xor_sync(0xffffffffu, Ss, o);
                k  += __shfl_xor_sync(0xffffffffu, k, o);
            }
            if (k == 0) break;
            const float delta = (Ss - 1.0f) / (float)k;
            tau += delta;
            if (fabsf(delta) < 1e-8f) break;
        }
    }

#pragma unroll 4
    for (int i = 0; i < 16; i++) {
        float4 v = r4[i * 32 + lane];
        float4 o;
        o.x = fmaxf(v.x - tau, 0.f); o.y = fmaxf(v.y - tau, 0.f);
        o.z = fmaxf(v.z - tau, 0.f); o.w = fmaxf(v.w - tau, 0.f);
        w4[i * 32 + lane] = o;
    }
}

// ======================= attn@V kernel (3xTF32) =======================
// P[q,d] = sum_k attn[q,k] V[k,d].  CTA: (bh, 128 q), 64 token-tiles of 32,
// double-buffered. B = V^T interleaved (1x LDS.128), A raw in-reg cvt.
#define AV_SMEM ((2 * 128 * 36 + 2 * 64 * 80) * 4)   // 77,824 B -> 2 CTAs/SM

__global__ __launch_bounds__(256, 2)
void attnv_kernel(const float* __restrict__ A)
{
    extern __shared__ float sm[];
    float* sA[2] = { sm, sm + 128 * 36 };
    float* sV[2] = { sm + 2 * 128 * 36, sm + 2 * 128 * 36 + 64 * 80 };
    uint32_t sAa[2] = { smem_u32(sA[0]), smem_u32(sA[1]) };
    uint32_t sVa[2] = { smem_u32(sV[0]), smem_u32(sV[1]) };

    const int tid = threadIdx.x;
    const int bh = blockIdx.y, q0 = blockIdx.x * 128;
    const int w = tid >> 5, lane = tid & 31;
    const int g = lane >> 2, t4 = lane & 3;
    const int lrA = tid >> 1, lcA = (tid & 1) * 16;   // A: 128 rows x 32 raw
    const int lrV = tid >> 2, lcV = (tid & 3) * 16;   // V^T: 64 d-rows x 64 ilv

    const float* arow = A + ((size_t)(bh * N_SEQ + q0 + lrA)) * N_SEQ + lcA;
    const float* vrow = g_Vti + ((size_t)bh * 64 + lrV) * 4096 + lcV;

    auto prefetch = [&](int kt, int buf) {
#pragma unroll
        for (int i = 0; i < 4; i++)
            cp16(sAa[buf] + (lrA * 36 + lcA + i * 4) * 4, arow + kt * 32 + i * 4);
#pragma unroll
        for (int i = 0; i < 4; i++)
            cp16(sVa[buf] + (lrV * 80 + lcV + i * 4) * 4, vrow + kt * 64 + i * 4);
        CP_COMMIT();
    };

    float acc[8][4];
#pragma unroll
    for (int i = 0; i < 8; i++)
#pragma unroll
        for (int j = 0; j < 4; j++) acc[i][j] = 0.f;

    prefetch(0, 0);
    for (int kt = 0; kt < 64; kt++) {
        const int buf = kt & 1;
        if (kt < 63) { prefetch(kt + 1, buf ^ 1); CP_WAIT(1); }
        else         { CP_WAIT(0); }
        __syncthreads();

#pragma unroll
        for (int kf = 0; kf < 4; kf++) {
            uint32_t ah[4], al[4];
            lda_hl(ah, al, sA[buf] + (w * 16 + g) * 36 + kf * 8 + t4, 36);
#pragma unroll
            for (int nf = 0; nf < 8; nf++) {
                float4 vb = *(const float4*)&sV[buf][(nf * 8 + g) * 80 + kf * 16 + t4 * 4];
                uint32_t bh2[2] = { __float_as_uint(vb.x), __float_as_uint(vb.y) };
                uint32_t bl2[2] = { __float_as_uint(vb.z), __float_as_uint(vb.w) };
                mma3(acc[nf], ah, al, bh2, bl2);
            }
        }
        __syncthreads();
    }

    const int b = bh >> 3, h = bh & 7;
    float* dst0 = g_P + ((size_t)(b * N_SEQ + q0 + w * 16 + g)) * C_DIM + h * 64;
    float* dst1 = dst0 + 8 * C_DIM;
#pragma unroll
    for (int nf = 0; nf < 8; nf++) {
        const int c = nf * 8 + t4 * 2;
        *(float2*)(dst0 + c) = make_float2(acc[nf][0], acc[nf][1]);
        *(float2*)(dst1 + c) = make_float2(acc[nf][2], acc[nf][3]);
    }
}

// ---------------------------------------------------------------------------
extern "C" void kernel_launch(void* const* d_in, const int* in_sizes, int n_in,
                              void* d_out, int out_size)
{
    const float* x  = (const float*)d_in[0];
    const float* Wq = (const float*)d_in[1];
    const float* bq = (const float*)d_in[2];
    const float* Wk = (const float*)d_in[3];
    const float* bk = (const float*)d_in[4];
    const float* Wv = (const float*)d_in[5];
    const float* bv = (const float*)d_in[6];
    const float* Wo = (const float*)d_in[7];
    const float* bo = (const float*)d_in[8];

    float *dP, *dS;
    cudaGetSymbolAddress((void**)&dP, g_P);
    cudaGetSymbolAddress((void**)&dS, g_S);

    float* out = (float*)d_out;
    const long long OUT_N = 2LL * N_SEQ * C_DIM;
    const long long ATT_N = (long long)N_BH * N_SEQ * N_SEQ;
    float* final_ptr = nullptr;
    float* attn_ptr  = nullptr;
    if ((long long)out_size >= OUT_N + ATT_N) { final_ptr = out; attn_ptr = out + OUT_N; }
    else if ((long long)out_size >= ATT_N)    { attn_ptr = out; }
    else                                      { final_ptr = out; }
    float* S = attn_ptr ? attn_ptr : dS;

    cudaFuncSetAttribute(proj_kernel,   cudaFuncAttributeMaxDynamicSharedMemorySize, PJ_SMEM);
    cudaFuncSetAttribute(scores_kernel, cudaFuncAttributeMaxDynamicSharedMemorySize, SC_SMEM);
    cudaFuncSetAttribute(attnv_kernel,  cudaFuncAttributeMaxDynamicSharedMemorySize, AV_SMEM);

    // pre-split weights into hi/lo interleaved; mats: 0=Wq 1=Wk 2=Wv 3=Wo
    wconv_kernel<<<dim3(C_DIM, 4), 128>>>(Wq, Wk, Wv, Wo);

    // Q/K/V projections in one launch (z selects weight + epilogue format)
    proj_kernel<<<dim3(32, 8, 3), 256, PJ_SMEM>>>(x, bq, bk, bv, bo, nullptr, 0);

    scores_kernel<<<dim3(16, 16), 256, SC_SMEM>>>(S);
    sparsemax_kernel<<<(N_BH * N_SEQ) / 8, 256>>>(S);
    attnv_kernel<<<dim3(16, 16), 256, AV_SMEM>>>(S);

    if (final_ptr)
        proj_kernel<<<dim3(32, 8, 1), 256, PJ_SMEM>>>(dP, bq, bk, bv, bo, final_ptr, 3);
}

// round 11
// speedup vs baseline: 2.8943x; 1.2008x over previous
#include <cuda_runtime.h>
#include <cstdint>

#define N_SEQ 2048
#define C_DIM 512
#define N_BH  16

// ---- device-global scratch (no allocation allowed) ----
__device__ float g_Qi [N_BH * N_SEQ * 128];   // Q hi/lo interleaved, 1/8 folded
__device__ float g_Ki [N_BH * N_SEQ * 128];   // K hi/lo interleaved
__device__ float g_V  [N_BH * N_SEQ * 64];    // raw V [bh][n][d]
__device__ float g_P  [2 * N_SEQ * C_DIM];
__device__ float g_S  [(size_t)N_BH * N_SEQ * N_SEQ];
__device__ float g_Wi [4 * C_DIM * 2 * C_DIM];// W hi/lo interleaved [mat][n][1024]
__device__ float g_rowmax[N_BH * N_SEQ];      // per-row score max (from scores)
__device__ int   g_ci [(size_t)N_BH * N_SEQ * 256];  // candidate indices
__device__ float g_cw [(size_t)N_BH * N_SEQ * 256];  // candidate weights
__device__ int   g_cn [N_BH * N_SEQ];                // candidate count (-1 = dense)

// ============================ helpers ============================
__device__ __forceinline__ uint32_t f2tf(float x) {
    uint32_t r; asm("cvt.rna.tf32.f32 %0, %1;" : "=r"(r) : "f"(x)); return r;
}
__device__ __forceinline__ uint32_t smem_u32(const void* p) {
    uint32_t a;
    asm("{ .reg .u64 t; cvta.to.shared.u64 t, %1; cvt.u32.u64 %0, t; }" : "=r"(a) : "l"(p));
    return a;
}
__device__ __forceinline__ void cp16(uint32_t s, const void* g) {
    asm volatile("cp.async.cg.shared.global [%0], [%1], 16;" :: "r"(s), "l"(g) : "memory");
}
#define CP_COMMIT() asm volatile("cp.async.commit_group;" ::: "memory")
#define CP_WAIT(n)  asm volatile("cp.async.wait_group %0;" :: "n"(n) : "memory")

__device__ __forceinline__ void mma8(float* d, const uint32_t* a, const uint32_t* b) {
    asm volatile(
        "mma.sync.aligned.m16n8k8.row.col.f32.tf32.tf32.f32 "
        "{%0,%1,%2,%3}, {%4,%5,%6,%7}, {%8,%9}, {%0,%1,%2,%3};"
        : "+f"(d[0]), "+f"(d[1]), "+f"(d[2]), "+f"(d[3])
        : "r"(a[0]), "r"(a[1]), "r"(a[2]), "r"(a[3]), "r"(b[0]), "r"(b[1]));
}
__device__ __forceinline__ void cvt_hl(float x, uint32_t& h, uint32_t& l) {
    h = f2tf(x);
    l = f2tf(x - __uint_as_float(h));
}
__device__ __forceinline__ void lda_hl(uint32_t* h, uint32_t* l, const float* p, int st) {
    cvt_hl(p[0], h[0], l[0]);
    cvt_hl(p[8 * st], h[1], l[1]);
    cvt_hl(p[4], h[2], l[2]);
    cvt_hl(p[8 * st + 4], h[3], l[3]);
}
__device__ __forceinline__ void mma3(float* acc, const uint32_t* ah, const uint32_t* al,
                                     const uint32_t* bh, const uint32_t* bl) {
    mma8(acc, ah, bh);
    mma8(acc, al, bh);
    mma8(acc, ah, bl);
}
// interleaved hi/lo position: 8-group of c -> 16 floats {h(p),h(p+4),l(p),l(p+4)}x4
__device__ __forceinline__ int ilv(int c) {
    return ((c & ~7) << 1) + ((c & 3) << 2) + ((c >> 2) & 1);
}
__device__ __forceinline__ float u2f(uint32_t x) { return __uint_as_float(x); }

// =================== weight pre-split (hi/lo interleaved) ===================
__global__ void wconv_kernel(const float* __restrict__ W0, const float* __restrict__ W1,
                             const float* __restrict__ W2, const float* __restrict__ W3)
{
    const int mat = blockIdx.y;
    const float* W = (mat == 0) ? W0 : (mat == 1) ? W1 : (mat == 2) ? W2 : W3;
    const int n = blockIdx.x;
    float* dst = g_Wi + ((size_t)mat * C_DIM + n) * 1024;
    for (int c = threadIdx.x; c < C_DIM; c += blockDim.x) {
        uint32_t h, l; cvt_hl(W[n * C_DIM + c], h, l);
        const int p = ilv(c);
        dst[p] = u2f(h); dst[p + 2] = u2f(l);
    }
}

// ======================= projection GEMM (3xTF32) =======================
// Y = X @ W^T + bias.  CTA: 128m x 64n, BK=32 double-buffered; 8 warps = 16m.
// z: 0=Q interleaved (1/8 folded), 1=K interleaved, 2=raw V scatter, 3=flat out.
#define PJ_SMEM ((2 * 128 * 36 + 2 * 64 * 80) * 4)   // 77,824 B -> 2 CTAs/SM

__global__ __launch_bounds__(256, 2)
void proj_kernel(const float* __restrict__ X,
                 const float* __restrict__ b0, const float* __restrict__ b1,
                 const float* __restrict__ b2, const float* __restrict__ b3,
                 float* __restrict__ out_final, int zbase)
{
    extern __shared__ float sm[];
    float* sX[2] = { sm, sm + 128 * 36 };
    float* sW[2] = { sm + 2 * 128 * 36, sm + 2 * 128 * 36 + 64 * 80 };
    uint32_t sXa[2] = { smem_u32(sX[0]), smem_u32(sX[1]) };
    uint32_t sWa[2] = { smem_u32(sW[0]), smem_u32(sW[1]) };

    const int z = zbase + blockIdx.z;
    const float* bias = (z == 0) ? b0 : (z == 1) ? b1 : (z == 2) ? b2 : b3;
    const float* Wi = g_Wi + (size_t)z * C_DIM * 1024;

    const int tid = threadIdx.x;
    const int m0 = blockIdx.x * 128, n0 = blockIdx.y * 64;
    const int w = tid >> 5, lane = tid & 31;
    const int g = lane >> 2, t4 = lane & 3;
    const int lrX = tid >> 1, lcX = (tid & 1) * 16;   // X: 128 rows x 32 raw
    const int lrW = tid >> 2, lcW = (tid & 3) * 16;   // Wi: 64 rows x 64 ilv

    const float* xrow = X + (size_t)(m0 + lrX) * C_DIM + lcX;
    const float* wrow = Wi + (size_t)(n0 + lrW) * 1024 + lcW;

    auto prefetch = [&](int t, int buf) {
#pragma unroll
        for (int i = 0; i < 4; i++)
            cp16(sXa[buf] + (lrX * 36 + lcX + i * 4) * 4, xrow + t * 32 + i * 4);
#pragma unroll
        for (int i = 0; i < 4; i++)
            cp16(sWa[buf] + (lrW * 80 + lcW + i * 4) * 4, wrow + t * 64 + i * 4);
        CP_COMMIT();
    };

    float acc[8][4];
#pragma unroll
    for (int i = 0; i < 8; i++)
#pragma unroll
        for (int j = 0; j < 4; j++) acc[i][j] = 0.f;

    prefetch(0, 0);
    for (int t = 0; t < 16; t++) {
        const int buf = t & 1;
        if (t < 15) { prefetch(t + 1, buf ^ 1); CP_WAIT(1); }
        else        { CP_WAIT(0); }
        __syncthreads();
#pragma unroll
        for (int kf = 0; kf < 4; kf++) {
            uint32_t ah[4], al[4];
            lda_hl(ah, al, sX[buf] + (w * 16 + g) * 36 + kf * 8 + t4, 36);
#pragma unroll
            for (int nf = 0; nf < 8; nf++) {
                float4 b4 = *(const float4*)&sW[buf][(nf * 8 + g) * 80 + kf * 16 + t4 * 4];
                uint32_t bh2[2] = { __float_as_uint(b4.x), __float_as_uint(b4.y) };
                uint32_t bl2[2] = { __float_as_uint(b4.z), __float_as_uint(b4.w) };
                mma3(acc[nf], ah, al, bh2, bl2);
            }
        }
        __syncthreads();
    }

    const int m = m0 + w * 16 + g;
#pragma unroll
    for (int nf = 0; nf < 8; nf++) {
        const int j = n0 + nf * 8 + t4 * 2;
        const float bx = bias[j], by = bias[j + 1];
        float v0 = acc[nf][0] + bx, v1 = acc[nf][1] + by;   // row m
        float v2 = acc[nf][2] + bx, v3 = acc[nf][3] + by;   // row m+8
        if (z == 3) {
            *(float2*)(out_final + (size_t)m * C_DIM + j)       = make_float2(v0, v1);
            *(float2*)(out_final + (size_t)(m + 8) * C_DIM + j) = make_float2(v2, v3);
        } else {
            const int b = m >> 11, n = m & 2047;
            const int h = j >> 6, d0 = j & 63;
            const int bh = b * 8 + h;
            uint32_t hh, ll;
            if (z == 0) {          // Q interleaved, scale 1/8 folded (exact)
                const size_t r0 = ((size_t)bh * N_SEQ + n) * 128;
                const size_t r1 = r0 + 8 * 128;
                const int i0 = ilv(d0), i1 = ilv(d0 + 1);
                cvt_hl(v0 * 0.125f, hh, ll); g_Qi[r0 + i0] = u2f(hh); g_Qi[r0 + i0 + 2] = u2f(ll);
                cvt_hl(v1 * 0.125f, hh, ll); g_Qi[r0 + i1] = u2f(hh); g_Qi[r0 + i1 + 2] = u2f(ll);
                cvt_hl(v2 * 0.125f, hh, ll); g_Qi[r1 + i0] = u2f(hh); g_Qi[r1 + i0 + 2] = u2f(ll);
                cvt_hl(v3 * 0.125f, hh, ll); g_Qi[r1 + i1] = u2f(hh); g_Qi[r1 + i1 + 2] = u2f(ll);
            } else if (z == 1) {   // K interleaved
                const size_t r0 = ((size_t)bh * N_SEQ + n) * 128;
                const size_t r1 = r0 + 8 * 128;
                const int i0 = ilv(d0), i1 = ilv(d0 + 1);
                cvt_hl(v0, hh, ll); g_Ki[r0 + i0] = u2f(hh); g_Ki[r0 + i0 + 2] = u2f(ll);
                cvt_hl(v1, hh, ll); g_Ki[r0 + i1] = u2f(hh); g_Ki[r0 + i1 + 2] = u2f(ll);
                cvt_hl(v2, hh, ll); g_Ki[r1 + i0] = u2f(hh); g_Ki[r1 + i0 + 2] = u2f(ll);
                cvt_hl(v3, hh, ll); g_Ki[r1 + i1] = u2f(hh); g_Ki[r1 + i1 + 2] = u2f(ll);
            } else {               // raw V [bh][n][d]
                *(float2*)(g_V + ((size_t)bh * N_SEQ + n) * 64 + d0)     = make_float2(v0, v1);
                *(float2*)(g_V + ((size_t)bh * N_SEQ + n + 8) * 64 + d0) = make_float2(v2, v3);
            }
        }
    }
}

// ======================= scores kernel (3xTF32) =======================
// S[q,:] = scaled Q K^T (scale folded into Q).  CTA: (bh, 128 q), 64 token-tiles
// of 32, double-buffered. Also emits per-row max into g_rowmax (fused, ~free).
#define SC_SMEM ((128 * 144 + 2 * 32 * 144) * 4)   // 110,592 B -> 2 CTAs/SM

__global__ __launch_bounds__(256, 2)
void scores_kernel(float* __restrict__ S)
{
    extern __shared__ float sm[];
    float* sQ = sm;                                    // 128 rows x 144
    float* sK[2] = { sm + 128 * 144, sm + 128 * 144 + 32 * 144 };
    const uint32_t sQa = smem_u32(sQ);
    uint32_t sKa[2] = { smem_u32(sK[0]), smem_u32(sK[1]) };

    const int tid = threadIdx.x;
    const int bh = blockIdx.y, q0 = blockIdx.x * 128;
    const int w = tid >> 5, lane = tid & 31;
    const int g = lane >> 2, t4 = lane & 3;

    {   // Q tile: 128 rows x 128 floats
        const int lr = tid >> 1, lc = (tid & 1) * 64;
        const float* qs = g_Qi + ((size_t)bh * N_SEQ + q0 + lr) * 128 + lc;
#pragma unroll
        for (int i = 0; i < 16; i++)
            cp16(sQa + (lr * 144 + lc + i * 4) * 4, qs + i * 4);
        CP_COMMIT();
    }
    const int lrK = tid >> 3, lcK = (tid & 7) * 16;   // 32 rows x 128 floats
    const float* krow = g_Ki + ((size_t)bh * N_SEQ + lrK) * 128 + lcK;
    auto prefetchK = [&](int kt, int buf) {
        const size_t off = (size_t)kt * 32 * 128;
#pragma unroll
        for (int i = 0; i < 4; i++)
            cp16(sKa[buf] + (lrK * 144 + lcK + i * 4) * 4, krow + off + i * 4);
        CP_COMMIT();
    };

    float m0 = -3.402823466e38f, m1 = -3.402823466e38f;   // row maxima

    prefetchK(0, 0);
    for (int kt = 0; kt < 64; kt++) {
        const int buf = kt & 1;
        if (kt < 63) { prefetchK(kt + 1, buf ^ 1); CP_WAIT(1); }
        else         { CP_WAIT(0); }
        __syncthreads();

        float acc[4][4];
#pragma unroll
        for (int i = 0; i < 4; i++)
#pragma unroll
            for (int j = 0; j < 4; j++) acc[i][j] = 0.f;

#pragma unroll
        for (int kf = 0; kf < 8; kf++) {
            float4 qa = *(const float4*)&sQ[(w * 16 + g) * 144 + kf * 16 + t4 * 4];
            float4 qb = *(const float4*)&sQ[(w * 16 + g + 8) * 144 + kf * 16 + t4 * 4];
            uint32_t ah[4] = { __float_as_uint(qa.x), __float_as_uint(qb.x),
                               __float_as_uint(qa.y), __float_as_uint(qb.y) };
            uint32_t al[4] = { __float_as_uint(qa.z), __float_as_uint(qb.z),
                               __float_as_uint(qa.w), __float_as_uint(qb.w) };
#pragma unroll
            for (int nf = 0; nf < 4; nf++) {
                float4 kb = *(const float4*)&sK[buf][(nf * 8 + g) * 144 + kf * 16 + t4 * 4];
                uint32_t bh2[2] = { __float_as_uint(kb.x), __float_as_uint(kb.y) };
                uint32_t bl2[2] = { __float_as_uint(kb.z), __float_as_uint(kb.w) };
                mma3(acc[nf], ah, al, bh2, bl2);
            }
        }
        __syncthreads();   // all warps done with sK[buf] before it is refilled

        float* dst0 = S + ((size_t)(bh * N_SEQ + q0 + w * 16 + g)) * N_SEQ + kt * 32;
        float* dst1 = dst0 + 8 * N_SEQ;
#pragma unroll
        for (int nf = 0; nf < 4; nf++) {
            m0 = fmaxf(m0, fmaxf(acc[nf][0], acc[nf][1]));
            m1 = fmaxf(m1, fmaxf(acc[nf][2], acc[nf][3]));
            const int c = nf * 8 + t4 * 2;
            *(float2*)(dst0 + c) = make_float2(acc[nf][0], acc[nf][1]);
            *(float2*)(dst1 + c) = make_float2(acc[nf][2], acc[nf][3]);
        }
    }

    m0 = fmaxf(m0, __shfl_xor_sync(0xffffffffu, m0, 1));
    m0 = fmaxf(m0, __shfl_xor_sync(0xffffffffu, m0, 2));
    m1 = fmaxf(m1, __shfl_xor_sync(0xffffffffu, m1, 1));
    m1 = fmaxf(m1, __shfl_xor_sync(0xffffffffu, m1, 2));
    if (t4 == 0) {
        g_rowmax[bh * N_SEQ + q0 + w * 16 + g]     = m0;
        g_rowmax[bh * N_SEQ + q0 + w * 16 + g + 8] = m1;
    }
}

// ======================= sparsemax kernel (v4) =======================
// Row per warp. Single read pass: filter candidates (> rowmax-1) into shared
// (value + index), Newton over <=8 register candidates -> tau. Writeback needs
// NO read: write zero float4s + scatter candidate weights (same-thread
// overlapping stores are program-ordered). Also emits the compacted candidate
// (idx, w) list for the sparse attn@V gather. Exact dense fallback if any lane
// overflows 8 candidates (g_cn = -1).
__global__ __launch_bounds__(256)
void spmax_kernel(float* __restrict__ A)
{
    __shared__ float cv[8 * 8 * 32];
    __shared__ int   cx[8 * 8 * 32];
    const int lane = threadIdx.x & 31;
    const int warp = threadIdx.x >> 5;
    const size_t row = (size_t)blockIdx.x * 8 + warp;
    const float4* r4 = (const float4*)(A + row * N_SEQ);
    float4* w4 = (float4*)(A + row * N_SEQ);

    const float thr = g_rowmax[row] - 1.0f;

    float* cwv = cv + warp * 256 + lane;
    int*   cwx = cx + warp * 256 + lane;
    int cnt = 0;
#pragma unroll 4
    for (int i = 0; i < 16; i++) {
        float4 v = r4[i * 32 + lane];
        float e[4] = { v.x, v.y, v.z, v.w };
#pragma unroll
        for (int c = 0; c < 4; c++) {
            if (e[c] > thr) {
                if (cnt < 8) { cwv[cnt * 32] = e[c]; cwx[cnt * 32] = (i * 32 + lane) * 4 + c; }
                cnt++;
            }
        }
    }
    __syncwarp();

    float tau = thr;
    if (__ballot_sync(0xffffffffu, cnt > 8)) {
        // dense fallback: exact full-scan Newton + dense writeback
        for (int it = 0; it < 64; ++it) {
            float Ss = 0.f; int k = 0;
#pragma unroll 4
            for (int i = 0; i < 16; i++) {
                float4 v = r4[i * 32 + lane];
                float d;
                d = v.x - tau; if (d > 0.f) { Ss += d; k++; }
                d = v.y - tau; if (d > 0.f) { Ss += d; k++; }
                d = v.z - tau; if (d > 0.f) { Ss += d; k++; }
                d = v.w - tau; if (d > 0.f) { Ss += d; k++; }
            }
#pragma unroll
            for (int o = 16; o; o >>= 1) {
                Ss += __shfl_xor_sync(0xffffffffu, Ss, o);
                k  += __shfl_xor_sync(0xffffffffu, k, o);
            }
            if (k == 0) break;
            const float delta = (Ss - 1.0f) / (float)k;
            tau += delta;
            if (fabsf(delta) < 1e-8f) break;
        }
#pragma unroll 4
        for (int i = 0; i < 16; i++) {
            float4 v = r4[i * 32 + lane];
            float4 o;
            o.x = fmaxf(v.x - tau, 0.f); o.y = fmaxf(v.y - tau, 0.f);
            o.z = fmaxf(v.z - tau, 0.f); o.w = fmaxf(v.w - tau, 0.f);
            w4[i * 32 + lane] = o;
        }
        if (lane == 0) g_cn[row] = -1;
    } else {
        float cb[8];
#pragma unroll
        for (int j = 0; j < 8; j++) cb[j] = cwv[j * 32];
        for (int it = 0; it < 64; ++it) {
            float Ss = 0.f; int k = 0;
#pragma unroll
            for (int j = 0; j < 8; j++) {
                float d = cb[j] - tau;
                if (j < cnt && d > 0.f) { Ss += d; k++; }
            }
#pragma unroll
            for (int o = 16; o; o >>= 1) {
                Ss += __shfl_xor_sync(0xffffffffu, Ss, o);
                k  += __shfl_xor_sync(0xffffffffu, k, o);
            }
            if (k == 0) break;
            const float delta = (Ss - 1.0f) / (float)k;
            tau += delta;
            if (fabsf(delta) < 1e-8f) break;
        }

        // compacted candidate list for the sparse gather
        int incl = cnt;
#pragma unroll
        for (int o = 1; o < 32; o <<= 1) {
            int t = __shfl_up_sync(0xffffffffu, incl, o);
            if (lane >= o) incl += t;
        }
        const int excl = incl - cnt;
        const int total = __shfl_sync(0xffffffffu, incl, 31);
        const size_t base = row * 256;
#pragma unroll
        for (int j = 0; j < 8; j++) {
            if (j < cnt) {
                g_cw[base + excl + j] = fmaxf(cb[j] - tau, 0.f);
                g_ci[base + excl + j] = cwx[j * 32];
            }
        }
        if (lane == 0) g_cn[row] = total;

        // writeback: zeros (no read) + scatter candidate weights
        const float4 z = make_float4(0.f, 0.f, 0.f, 0.f);
#pragma unroll 4
        for (int i = 0; i < 16; i++) w4[i * 32 + lane] = z;
#pragma unroll
        for (int j = 0; j < 8; j++) {
            if (j < cnt)
                A[row * N_SEQ + cwx[j * 32]] = fmaxf(cb[j] - tau, 0.f);
        }
    }
}

// ======================= sparse attn@V gather =======================
// P[q,:] = sum_j w_j * V[idx_j,:].  Warp per row; lane owns 2 d-columns.
// Dense fallback (g_cn < 0) scans the written attn row.
__global__ __launch_bounds__(256)
void spav_kernel(const float* __restrict__ A)
{
    const int lane = threadIdx.x & 31;
    const int warp = threadIdx.x >> 5;
    const size_t row = (size_t)blockIdx.x * 8 + warp;
    const int bh = (int)(row >> 11), q = (int)(row & 2047);
    const float* Vb = g_V + ((size_t)bh * N_SEQ) * 64;
    const int d = lane * 2;

    float ax = 0.f, ay = 0.f;
    const int n = g_cn[row];
    if (n >= 0) {
        const int*   ci = g_ci + row * 256;
        const float* cw = g_cw + row * 256;
        int j = 0;
        for (; j + 4 <= n; j += 4) {
            int   i0 = ci[j], i1 = ci[j+1], i2 = ci[j+2], i3 = ci[j+3];
            float w0 = cw[j], w1 = cw[j+1], w2 = cw[j+2], w3 = cw[j+3];
            float2 v0 = *(const float2*)(Vb + (size_t)i0 * 64 + d);
            float2 v1 = *(const float2*)(Vb + (size_t)i1 * 64 + d);
            float2 v2 = *(const float2*)(Vb + (size_t)i2 * 64 + d);
            float2 v3 = *(const float2*)(Vb + (size_t)i3 * 64 + d);
            ax += w0 * v0.x + w1 * v1.x + w2 * v2.x + w3 * v3.x;
            ay += w0 * v0.y + w1 * v1.y + w2 * v2.y + w3 * v3.y;
        }
        for (; j < n; j++) {
            int i0 = ci[j]; float w0 = cw[j];
            float2 v0 = *(const float2*)(Vb + (size_t)i0 * 64 + d);
            ax += w0 * v0.x; ay += w0 * v0.y;
        }
    } else {
        const float* Arow = A + row * N_SEQ;
        for (int k = 0; k < N_SEQ; k++) {
            float a = Arow[k];
            if (a != 0.f) {
                float2 v = *(const float2*)(Vb + (size_t)k * 64 + d);
                ax += a * v.x; ay += a * v.y;
            }
        }
    }

    const int b = bh >> 3, h = bh & 7;
    *(float2*)(g_P + ((size_t)(b * N_SEQ + q)) * C_DIM + h * 64 + d) = make_float2(ax, ay);
}

// ---------------------------------------------------------------------------
extern "C" void kernel_launch(void* const* d_in, const int* in_sizes, int n_in,
                              void* d_out, int out_size)
{
    const float* x  = (const float*)d_in[0];
    const float* Wq = (const float*)d_in[1];
    const float* bq = (const float*)d_in[2];
    const float* Wk = (const float*)d_in[3];
    const float* bk = (const float*)d_in[4];
    const float* Wv = (const float*)d_in[5];
    const float* bv = (const float*)d_in[6];
    const float* Wo = (const float*)d_in[7];
    const float* bo = (const float*)d_in[8];

    float *dP, *dS;
    cudaGetSymbolAddress((void**)&dP, g_P);
    cudaGetSymbolAddress((void**)&dS, g_S);

    float* out = (float*)d_out;
    const long long OUT_N = 2LL * N_SEQ * C_DIM;
    const long long ATT_N = (long long)N_BH * N_SEQ * N_SEQ;
    float* final_ptr = nullptr;
    float* attn_ptr  = nullptr;
    if ((long long)out_size >= OUT_N + ATT_N) { final_ptr = out; attn_ptr = out + OUT_N; }
    else if ((long long)out_size >= ATT_N)    { attn_ptr = out; }
    else                                      { final_ptr = out; }
    float* S = attn_ptr ? attn_ptr : dS;

    cudaFuncSetAttribute(proj_kernel,   cudaFuncAttributeMaxDynamicSharedMemorySize, PJ_SMEM);
    cudaFuncSetAttribute(scores_kernel, cudaFuncAttributeMaxDynamicSharedMemorySize, SC_SMEM);

    // pre-split weights into hi/lo interleaved; mats: 0=Wq 1=Wk 2=Wv 3=Wo
    wconv_kernel<<<dim3(C_DIM, 4), 128>>>(Wq, Wk, Wv, Wo);

    // Q/K/V projections in one launch (z selects weight + epilogue format)
    proj_kernel<<<dim3(32, 8, 3), 256, PJ_SMEM>>>(x, bq, bk, bv, bo, nullptr, 0);

    scores_kernel<<<dim3(16, 16), 256, SC_SMEM>>>(S);
    spmax_kernel<<<(N_BH * N_SEQ) / 8, 256>>>(S);
    spav_kernel<<<(N_BH * N_SEQ) / 8, 256>>>(S);

    if (final_ptr)
        proj_kernel<<<dim3(32, 8, 1), 256, PJ_SMEM>>>(dP, bq, bk, bv, bo, final_ptr, 3);
}